// round 2
// baseline (speedup 1.0000x reference)
#include <cuda_runtime.h>
#include <math.h>

#define B_ 8192
#define D_ 512
#define C_ 1000
#define K_ 8
#define EPSV 1e-8f
#define TEMPV 0.2f
#define NEGV -10000.0f

// Scratch (allowed: __device__ globals, no runtime allocation)
__device__ float g_h[(size_t)K_ * B_ * D_];          // [k][b][d]   134 MB
__device__ float g_logits[(size_t)B_ * K_ * C_];     // [b][k][c]   262 MB

// ---------------------------------------------------------------------------
// Tiled fp32 GEMM: Cout[m, n] = act( sum_k A[m,k] * W[k,n] + bias[n] )
// Block tile 128x64, BK=16, thread tile 8x4, 256 threads.
// Batched over blockIdx.z with independent strides.
// ---------------------------------------------------------------------------
template <bool RELU>
__global__ void __launch_bounds__(256) gemm_kernel(
    const float* __restrict__ A, long long aBatchStride, int ldA,
    const float* __restrict__ W, long long wBatchStride, int ldW,
    const float* __restrict__ bias, long long biasBatchStride,
    float* __restrict__ Cout, long long cBatchOff, int ldC,
    int M, int N, int Kd)
{
    constexpr int BM = 128, BN = 64, BK = 16;

    __shared__ float As[BK][BM];      // stored transposed: [k][m]
    __shared__ float Bs[BK][BN];

    const int bz = blockIdx.z;
    const float* Ab = A + (size_t)bz * aBatchStride;
    const float* Wb = W + (size_t)bz * wBatchStride;
    const float* biasb = bias + (size_t)bz * biasBatchStride;
    float* Cb = Cout + (size_t)bz * cBatchOff;

    const int n0 = blockIdx.x * BN;
    const int m0 = blockIdx.y * BM;
    const int tid = threadIdx.x;
    const int tx = tid & 15;          // 0..15 (N direction)
    const int ty = tid >> 4;          // 0..15 (M direction)

    // A-load mapping: 128 rows x 4 float4-cols, 256 threads -> 2 float4 each
    const int arow = tid & 127;       // 0..127
    const int akc  = tid >> 7;        // 0..1 (and +2)
    // B-load mapping: 16 rows x 16 float4-cols -> 1 float4 each
    const int brow = tid >> 4;        // 0..15
    const int bcol = (tid & 15) * 4;  // 0..60

    float acc[8][4];
#pragma unroll
    for (int i = 0; i < 8; i++)
#pragma unroll
        for (int j = 0; j < 4; j++) acc[i][j] = 0.0f;

    for (int kk = 0; kk < Kd; kk += BK) {
        // --- load A tile (transposed into smem) ---
#pragma unroll
        for (int r = 0; r < 2; r++) {
            int kc = (akc + 2 * r) * 4;  // 0,4,8,12
            float4 v = *(const float4*)(Ab + (size_t)(m0 + arow) * ldA + kk + kc);
            As[kc + 0][arow] = v.x;
            As[kc + 1][arow] = v.y;
            As[kc + 2][arow] = v.z;
            As[kc + 3][arow] = v.w;
        }
        // --- load B tile ---
        {
            int col = n0 + bcol;
            float4 v = make_float4(0.f, 0.f, 0.f, 0.f);
            if (col < N)  // N is a multiple of 4, so a float4 is fully in or out
                v = *(const float4*)(Wb + (size_t)(kk + brow) * ldW + col);
            *(float4*)(&Bs[brow][bcol]) = v;
        }
        __syncthreads();

#pragma unroll
        for (int k = 0; k < BK; k++) {
            float a[8], b[4];
            float4 a0 = *(const float4*)(&As[k][ty * 8]);
            float4 a1 = *(const float4*)(&As[k][ty * 8 + 4]);
            a[0] = a0.x; a[1] = a0.y; a[2] = a0.z; a[3] = a0.w;
            a[4] = a1.x; a[5] = a1.y; a[6] = a1.z; a[7] = a1.w;
            float4 bv = *(const float4*)(&Bs[k][tx * 4]);
            b[0] = bv.x; b[1] = bv.y; b[2] = bv.z; b[3] = bv.w;
#pragma unroll
            for (int i = 0; i < 8; i++)
#pragma unroll
                for (int j = 0; j < 4; j++)
                    acc[i][j] = fmaf(a[i], b[j], acc[i][j]);
        }
        __syncthreads();
    }

    // --- epilogue ---
#pragma unroll
    for (int j = 0; j < 4; j++) {
        int col = n0 + tx * 4 + j;
        if (col < N) {
            float bv = biasb[col];
#pragma unroll
            for (int i = 0; i < 8; i++) {
                float v = acc[i][j] + bv;
                if (RELU) v = fmaxf(v, 0.0f);
                Cb[(size_t)(m0 + ty * 8 + i) * ldC + col] = v;
            }
        }
    }
}

// ---------------------------------------------------------------------------
// Gating kernel: one block per batch row.
// Computes per-expert softmax stats, the probs Gram matrix, the greedy
// diversity selection (exact replication of the jax loop incl. first-index
// argmax tie-break), gate softmax, and the gated logit combine.
// Dynamic smem: 8000 logits + 8000 exps = 64000 bytes.
// ---------------------------------------------------------------------------
__global__ void __launch_bounds__(256) gating_kernel(
    const int* __restrict__ n_exp,
    float* __restrict__ out_logits,
    float* __restrict__ out_gates)
{
    extern __shared__ float sm[];
    float* sl = sm;                 // [K_ * C_] raw logits
    float* se = sm + K_ * C_;       // [K_ * C_] exp(l - max)

    __shared__ float sZ[K_];
    __shared__ float sG[K_ * K_];
    __shared__ float sgate[K_];

    const int b = blockIdx.x;
    const int tid = threadIdx.x;
    const int w = tid >> 5, lane = tid & 31;

    const float* lrow = g_logits + (size_t)b * K_ * C_;
    for (int i = tid; i < K_ * C_; i += 256) sl[i] = lrow[i];
    __syncthreads();

    // per-expert max and Z (one warp per expert; 256 threads = 8 warps = K_)
    {
        float m = -INFINITY;
        for (int c = lane; c < C_; c += 32) m = fmaxf(m, sl[w * C_ + c]);
#pragma unroll
        for (int o = 16; o > 0; o >>= 1) m = fmaxf(m, __shfl_xor_sync(0xffffffffu, m, o));
        float z = 0.0f;
        for (int c = lane; c < C_; c += 32) {
            float e = __expf(sl[w * C_ + c] - m);
            se[w * C_ + c] = e;
            z += e;
        }
#pragma unroll
        for (int o = 16; o > 0; o >>= 1) z += __shfl_xor_sync(0xffffffffu, z, o);
        if (lane == 0) sZ[w] = z;
    }
    __syncthreads();

    // Gram of softmax probs: G[i][j] = (sum_c e_i e_j) / (Z_i Z_j); 36 pairs
    for (int p = w; p < 36; p += 8) {
        int i = 0, q = p;
        while (q >= K_ - i) { q -= (K_ - i); i++; }
        int j = i + q;
        float s = 0.0f;
        for (int c = lane; c < C_; c += 32) s += se[i * C_ + c] * se[j * C_ + c];
#pragma unroll
        for (int o = 16; o > 0; o >>= 1) s += __shfl_xor_sync(0xffffffffu, s, o);
        if (lane == 0) {
            float g = s / (sZ[i] * sZ[j]);
            sG[i * K_ + j] = g;
            sG[j * K_ + i] = g;
        }
    }
    __syncthreads();

    // Serial selection on thread 0 (K=8, trivial)
    if (tid == 0) {
        float Smat[K_][K_], conf[K_], nrm[K_];
#pragma unroll
        for (int i = 0; i < K_; i++) {
            nrm[i] = sqrtf(sG[i * K_ + i]) + EPSV;
            conf[i] = 1.0f / sZ[i];  // max prob = exp(lmax-lmax)/Z
        }
#pragma unroll
        for (int i = 0; i < K_; i++)
#pragma unroll
            for (int j = 0; j < K_; j++)
                Smat[i][j] = sG[i * K_ + j] / (nrm[i] * nrm[j]);

        // argmax conf (first-index on ties, matching jnp.argmax)
        int bi = 0; float bv = conf[0];
#pragma unroll
        for (int i = 1; i < K_; i++) if (conf[i] > bv) { bv = conf[i]; bi = i; }
        bool sel[K_];
#pragma unroll
        for (int i = 0; i < K_; i++) sel[i] = false;
        sel[bi] = true;

        int n = n_exp[b];
        for (int t = 1; t < K_; t++) {
            float dist[K_];
#pragma unroll
            for (int i = 0; i < K_; i++) {
                if (sel[i]) { dist[i] = -INFINITY; }
                else {
                    float ms = -INFINITY;
#pragma unroll
                    for (int j = 0; j < K_; j++)
                        if (sel[j]) ms = fmaxf(ms, Smat[i][j]);
                    dist[i] = 1.0f - ms;
                }
            }
            int ai = 0; float av = dist[0];
#pragma unroll
            for (int i = 1; i < K_; i++) if (dist[i] > av) { av = dist[i]; ai = i; }
            if (t < n) sel[ai] = true;
        }

        float gl[K_], gm = -INFINITY;
#pragma unroll
        for (int i = 0; i < K_; i++) {
            gl[i] = (sel[i] ? conf[i] : NEGV) / TEMPV;
            gm = fmaxf(gm, gl[i]);
        }
        float gs = 0.0f;
#pragma unroll
        for (int i = 0; i < K_; i++) { gl[i] = __expf(gl[i] - gm); gs += gl[i]; }
#pragma unroll
        for (int i = 0; i < K_; i++) sgate[i] = gl[i] / gs;
    }
    __syncthreads();

    // gated combine of raw logits
    for (int c = tid; c < C_; c += 256) {
        float v = 0.0f;
#pragma unroll
        for (int k = 0; k < K_; k++) v += sgate[k] * sl[k * C_ + c];
        out_logits[(size_t)b * C_ + c] = v;
    }
    if (tid < K_) out_gates[(size_t)b * K_ + tid] = sgate[tid];
}

// ---------------------------------------------------------------------------
extern "C" void kernel_launch(void* const* d_in, const int* in_sizes, int n_in,
                              void* d_out, int out_size)
{
    const float* z    = (const float*)d_in[0];
    const int*   nexp = (const int*)d_in[1];
    const float* W1   = (const float*)d_in[2];
    const float* b1   = (const float*)d_in[3];
    const float* W2   = (const float*)d_in[4];
    const float* b2   = (const float*)d_in[5];
    float* out = (float*)d_out;

    float* hbuf = nullptr;
    float* lbuf = nullptr;
    cudaGetSymbolAddress((void**)&hbuf, g_h);
    cudaGetSymbolAddress((void**)&lbuf, g_logits);

    dim3 blk(256);

    // GEMM1: h[k][b][:] = relu(z[b] @ W1[k] + b1[k])   (M=B, N=D, Kd=D)
    dim3 g1(D_ / 64, B_ / 128, K_);
    gemm_kernel<true><<<g1, blk>>>(
        z, 0LL, D_,
        W1, (long long)D_ * D_, D_,
        b1, (long long)D_,
        hbuf, (long long)B_ * D_, D_,
        B_, D_, D_);

    // GEMM2: logits[b][k][:] = h[k][b] @ W2[k] + b2[k]  (M=B, N=C, Kd=D)
    dim3 g2((C_ + 63) / 64, B_ / 128, K_);
    gemm_kernel<false><<<g2, blk>>>(
        hbuf, (long long)B_ * D_, D_,
        W2, (long long)D_ * C_, C_,
        b2, (long long)C_,
        lbuf, (long long)C_, K_ * C_,
        B_, C_, D_);

    // Gating + combine
    cudaFuncSetAttribute(gating_kernel,
                         cudaFuncAttributeMaxDynamicSharedMemorySize, 65536);
    gating_kernel<<<B_, 256, 2 * K_ * C_ * sizeof(float)>>>(
        nexp, out, out + (size_t)B_ * C_);
}

// round 4
// speedup vs baseline: 1.3759x; 1.3759x over previous
#include <cuda_runtime.h>
#include <cuda_bf16.h>
#include <cstdint>
#include <math.h>

#define B_ 8192
#define D_ 512
#define C_ 1000
#define CP_ 1024
#define K_ 8
#define EPSV 1e-8f
#define TEMPV 0.2f
#define NEGV -10000.0f

// ---------------------------------------------------------------------------
// Scratch (__device__ globals)
// ---------------------------------------------------------------------------
__device__ __nv_bfloat16 g_z0[(size_t)B_ * D_];
__device__ __nv_bfloat16 g_z1[(size_t)B_ * D_];
__device__ __nv_bfloat16 g_z2[(size_t)B_ * D_];
__device__ __nv_bfloat16 g_w1t0[(size_t)K_ * D_ * D_];
__device__ __nv_bfloat16 g_w1t1[(size_t)K_ * D_ * D_];
__device__ __nv_bfloat16 g_w1t2[(size_t)K_ * D_ * D_];
__device__ __nv_bfloat16 g_w2t0[(size_t)K_ * CP_ * D_];
__device__ __nv_bfloat16 g_w2t1[(size_t)K_ * CP_ * D_];
__device__ __nv_bfloat16 g_w2t2[(size_t)K_ * CP_ * D_];
__device__ __nv_bfloat16 g_h0[(size_t)K_ * B_ * D_];
__device__ __nv_bfloat16 g_h1[(size_t)K_ * B_ * D_];
__device__ __nv_bfloat16 g_h2[(size_t)K_ * B_ * D_];
__device__ float g_logits[(size_t)B_ * K_ * CP_];

// ---------------------------------------------------------------------------
// PTX helpers
// ---------------------------------------------------------------------------
__device__ __forceinline__ uint32_t smem_u32(const void* p) {
    uint32_t a;
    asm("{ .reg .u64 t; cvta.to.shared.u64 t, %1; cvt.u32.u64 %0, t; }" : "=r"(a) : "l"(p));
    return a;
}
__device__ __forceinline__ void cp_async16(uint32_t s, const void* g) {
    asm volatile("cp.async.cg.shared.global [%0], [%1], 16;" :: "r"(s), "l"(g));
}
__device__ __forceinline__ void cp_commit() { asm volatile("cp.async.commit_group;"); }
template <int N>
__device__ __forceinline__ void cp_wait() { asm volatile("cp.async.wait_group %0;" :: "n"(N)); }

__device__ __forceinline__ void ldsm4(uint32_t* r, uint32_t addr) {
    asm volatile("ldmatrix.sync.aligned.m8n8.x4.shared.b16 {%0,%1,%2,%3}, [%4];"
                 : "=r"(r[0]), "=r"(r[1]), "=r"(r[2]), "=r"(r[3]) : "r"(addr));
}
__device__ __forceinline__ void mma16816(float* c, const uint32_t* a, uint32_t b0, uint32_t b1) {
    asm volatile(
        "mma.sync.aligned.m16n8k16.row.col.f32.bf16.bf16.f32 "
        "{%0,%1,%2,%3}, {%4,%5,%6,%7}, {%8,%9}, {%0,%1,%2,%3};"
        : "+f"(c[0]), "+f"(c[1]), "+f"(c[2]), "+f"(c[3])
        : "r"(a[0]), "r"(a[1]), "r"(a[2]), "r"(a[3]), "r"(b0), "r"(b1));
}

// 3-limb bf16 split: x = a + b + c + O(2^-25 |x|)
__device__ __forceinline__ void split3(float x, __nv_bfloat16& a, __nv_bfloat16& b,
                                       __nv_bfloat16& c) {
    a = __float2bfloat16(x);
    float r = x - __bfloat162float(a);
    b = __float2bfloat16(r);
    r = r - __bfloat162float(b);
    c = __float2bfloat16(r);
}

// ---------------------------------------------------------------------------
// Conversion kernels
// ---------------------------------------------------------------------------
__global__ void split3_kernel(const float* __restrict__ x, __nv_bfloat16* __restrict__ o0,
                              __nv_bfloat16* __restrict__ o1, __nv_bfloat16* __restrict__ o2,
                              int n) {
    int i = blockIdx.x * blockDim.x + threadIdx.x;
    if (i < n) split3(x[i], o0[i], o1[i], o2[i]);
}

// in: [K][D_][Nin] fp32 -> out: [K][Npad][D_] bf16 x3 (transposed, rows >= Nin zeroed)
__global__ void trsplit_kernel(const float* __restrict__ in, __nv_bfloat16* __restrict__ o0,
                               __nv_bfloat16* __restrict__ o1, __nv_bfloat16* __restrict__ o2,
                               int Nin, int Npad) {
    __shared__ float t[32][33];
    const int k = blockIdx.z;
    const int n0 = blockIdx.x * 32, d0 = blockIdx.y * 32;
    const int tx = threadIdx.x, ty = threadIdx.y;
    const float* src = in + (size_t)k * D_ * Nin;
#pragma unroll
    for (int r = 0; r < 4; r++) {
        int d = d0 + ty + r * 8, n = n0 + tx;
        t[ty + r * 8][tx] = (n < Nin) ? src[(size_t)d * Nin + n] : 0.0f;
    }
    __syncthreads();
    size_t obase = (size_t)k * Npad * D_;
#pragma unroll
    for (int r = 0; r < 4; r++) {
        int nl = ty + r * 8;
        float v = t[tx][nl];
        __nv_bfloat16 a, b, c;
        split3(v, a, b, c);
        size_t oi = obase + (size_t)(n0 + nl) * D_ + d0 + tx;
        o0[oi] = a; o1[oi] = b; o2[oi] = c;
    }
}

// ---------------------------------------------------------------------------
// HMMA (mma.sync bf16) GEMM with 6-product split.
// Block 128x128, BK=32, 256 threads (8 warps: 2x4), warp tile 64x32.
// Both GEMMs have Kd = 512 (row stride 1024B for all operands).
// ---------------------------------------------------------------------------
#define SPAD 40                      // smem row stride in bf16 (80B, conflict-free)
#define TILE_B (128 * SPAD * 2)      // 10240 B per limb tile
#define STAGE_B (6 * TILE_B)         // 61440 B
#define NCHUNK 16                    // 512 / 32

template <bool SPLIT>
__global__ void __launch_bounds__(256, 1) tc_gemm(
    const __nv_bfloat16* __restrict__ A0, const __nv_bfloat16* __restrict__ A1,
    const __nv_bfloat16* __restrict__ A2, long long aStr,
    const __nv_bfloat16* __restrict__ B0, const __nv_bfloat16* __restrict__ B1,
    const __nv_bfloat16* __restrict__ B2, long long bStr,
    const float* __restrict__ bias, int biasStr, int Nreal,
    float* __restrict__ outF, int outLd,
    __nv_bfloat16* __restrict__ O0, __nv_bfloat16* __restrict__ O1,
    __nv_bfloat16* __restrict__ O2)
{
    extern __shared__ __align__(16) char dsm[];
    const uint32_t sbase = smem_u32(dsm);

    const int tid = threadIdx.x;
    const int warp = tid >> 5, lane = tid & 31;
    const int bz = blockIdx.z;
    const int m0 = blockIdx.y * 128, n0 = blockIdx.x * 128;
    const int warpM = (warp >> 2) * 64;   // 0 or 64
    const int warpN = (warp & 3) * 32;    // 0,32,64,96

    const char* gp[6];
    gp[0] = (const char*)A0 + ((size_t)bz * aStr + (size_t)m0 * D_) * 2;
    gp[1] = (const char*)A1 + ((size_t)bz * aStr + (size_t)m0 * D_) * 2;
    gp[2] = (const char*)A2 + ((size_t)bz * aStr + (size_t)m0 * D_) * 2;
    gp[3] = (const char*)B0 + ((size_t)bz * bStr + (size_t)n0 * D_) * 2;
    gp[4] = (const char*)B1 + ((size_t)bz * bStr + (size_t)n0 * D_) * 2;
    gp[5] = (const char*)B2 + ((size_t)bz * bStr + (size_t)n0 * D_) * 2;

    auto load_stage = [&](int kk, int buf) {
#pragma unroll
        for (int t = 0; t < 6; t++) {
            uint32_t sb = sbase + buf * STAGE_B + t * TILE_B;
            const char* g = gp[t] + (size_t)kk * 64;   // 32 bf16 = 64B chunk
#pragma unroll
            for (int i = 0; i < 2; i++) {
                int idx = tid + i * 256;
                int row = idx >> 2, c = idx & 3;
                cp_async16(sb + row * 80 + c * 16, g + (size_t)row * 1024 + c * 16);
            }
        }
        cp_commit();
    };

    float acc[4][4][4];
#pragma unroll
    for (int i = 0; i < 4; i++)
#pragma unroll
        for (int j = 0; j < 4; j++)
#pragma unroll
            for (int r = 0; r < 4; r++) acc[i][j][r] = 0.0f;

    load_stage(0, 0);
    load_stage(1, 1);

    // product list: (a0b0, a0b1, a1b0, a1b1, a0b2, a2b0)
    constexpr int LA[6] = {0, 0, 1, 1, 0, 2};
    constexpr int LB[6] = {0, 1, 0, 1, 2, 0};

    for (int kk = 0; kk < NCHUNK; kk++) {
        const int buf = kk & 1;
        if (kk == NCHUNK - 1) cp_wait<0>(); else cp_wait<1>();
        __syncthreads();

        const uint32_t sb = sbase + buf * STAGE_B;
        // per-lane ldmatrix base offsets
        const uint32_t aRowOff = (uint32_t)(warpM + (lane & 15)) * 80 + (lane >> 4) * 16;
        const uint32_t bRowOff = (uint32_t)(warpN + (lane & 7) + ((lane >> 4) & 1) * 8) * 80 +
                                 ((lane >> 3) & 1) * 16;

#pragma unroll
        for (int ks = 0; ks < 2; ks++) {
            uint32_t afr[3][4][4];   // [limb][mfrag][reg]
            uint32_t bfr[3][2][4];   // [limb][jpair][reg]  (jpair covers 16 n)
#pragma unroll
            for (int p = 0; p < 3; p++) {
#pragma unroll
                for (int i = 0; i < 4; i++)
                    ldsm4(afr[p][i], sb + p * TILE_B + aRowOff + i * 16 * 80 + ks * 32);
#pragma unroll
                for (int jp = 0; jp < 2; jp++)
                    ldsm4(bfr[p][jp], sb + (3 + p) * TILE_B + bRowOff + jp * 16 * 80 + ks * 32);
            }
#pragma unroll
            for (int p = 0; p < 6; p++) {
#pragma unroll
                for (int i = 0; i < 4; i++)
#pragma unroll
                    for (int j = 0; j < 4; j++)
                        mma16816(acc[i][j], afr[LA[p]][i],
                                 bfr[LB[p]][j >> 1][(j & 1) * 2],
                                 bfr[LB[p]][j >> 1][(j & 1) * 2 + 1]);
            }
        }
        __syncthreads();
        if (kk + 2 < NCHUNK) load_stage(kk + 2, buf);
    }

    // ---------------- epilogue ----------------
    const int mBase = m0 + warpM + (lane >> 2);
    const int nBase = n0 + warpN + (lane & 3) * 2;
#pragma unroll
    for (int i = 0; i < 4; i++) {
#pragma unroll
        for (int j = 0; j < 4; j++) {
#pragma unroll
            for (int half = 0; half < 2; half++) {
                const int m = mBase + i * 16 + half * 8;
                const int n = nBase + j * 8;
                float v0 = acc[i][j][half * 2];
                float v1 = acc[i][j][half * 2 + 1];
                if (SPLIT) {
                    v0 = fmaxf(v0 + bias[bz * biasStr + n], 0.0f);
                    v1 = fmaxf(v1 + bias[bz * biasStr + n + 1], 0.0f);
                    __nv_bfloat16 a0, b0, c0, a1, b1, c1;
                    split3(v0, a0, b0, c0);
                    split3(v1, a1, b1, c1);
                    size_t ob = ((size_t)bz * B_ + m) * D_ + n;
                    *(__nv_bfloat162*)&O0[ob] = __nv_bfloat162(a0, a1);
                    *(__nv_bfloat162*)&O1[ob] = __nv_bfloat162(b0, b1);
                    *(__nv_bfloat162*)&O2[ob] = __nv_bfloat162(c0, c1);
                } else {
                    if (n < Nreal) {
                        v0 += bias[bz * biasStr + n];
                        v1 += bias[bz * biasStr + n + 1];
                    }
                    float2 vv = make_float2(v0, v1);
                    *(float2*)&outF[((size_t)m * K_ + bz) * outLd + n] = vv;
                }
            }
        }
    }
}

// ---------------------------------------------------------------------------
// Gating kernel (logits strided [b][k][CP_])
// ---------------------------------------------------------------------------
__global__ void __launch_bounds__(256) gating_kernel(
    const int* __restrict__ n_exp,
    float* __restrict__ out_logits,
    float* __restrict__ out_gates)
{
    extern __shared__ float sm[];
    float* sl = sm;             // [K_*C_]
    float* se = sm + K_ * C_;   // [K_*C_]
    __shared__ float sZ[K_], sG[K_ * K_], sgate[K_];

    const int b = blockIdx.x, tid = threadIdx.x;
    const int w = tid >> 5, lane = tid & 31;

    const float* lrow = g_logits + (size_t)b * K_ * CP_;
    for (int i = tid; i < K_ * C_; i += 256) {
        int k = i / C_, c = i - k * C_;
        sl[i] = lrow[(size_t)k * CP_ + c];
    }
    __syncthreads();

    {
        float m = -INFINITY;
        for (int c = lane; c < C_; c += 32) m = fmaxf(m, sl[w * C_ + c]);
#pragma unroll
        for (int o = 16; o > 0; o >>= 1) m = fmaxf(m, __shfl_xor_sync(0xffffffffu, m, o));
        float z = 0.0f;
        for (int c = lane; c < C_; c += 32) {
            float e = __expf(sl[w * C_ + c] - m);
            se[w * C_ + c] = e;
            z += e;
        }
#pragma unroll
        for (int o = 16; o > 0; o >>= 1) z += __shfl_xor_sync(0xffffffffu, z, o);
        if (lane == 0) sZ[w] = z;
    }
    __syncthreads();

    for (int p = w; p < 36; p += 8) {
        int i = 0, q = p;
        while (q >= K_ - i) { q -= (K_ - i); i++; }
        int j = i + q;
        float s = 0.0f;
        for (int c = lane; c < C_; c += 32) s += se[i * C_ + c] * se[j * C_ + c];
#pragma unroll
        for (int o = 16; o > 0; o >>= 1) s += __shfl_xor_sync(0xffffffffu, s, o);
        if (lane == 0) {
            float g = s / (sZ[i] * sZ[j]);
            sG[i * K_ + j] = g;
            sG[j * K_ + i] = g;
        }
    }
    __syncthreads();

    if (tid == 0) {
        float Smat[K_][K_], conf[K_], nrm[K_];
#pragma unroll
        for (int i = 0; i < K_; i++) {
            nrm[i] = sqrtf(sG[i * K_ + i]) + EPSV;
            conf[i] = 1.0f / sZ[i];
        }
#pragma unroll
        for (int i = 0; i < K_; i++)
#pragma unroll
            for (int j = 0; j < K_; j++)
                Smat[i][j] = sG[i * K_ + j] / (nrm[i] * nrm[j]);

        int bi = 0; float bv = conf[0];
#pragma unroll
        for (int i = 1; i < K_; i++) if (conf[i] > bv) { bv = conf[i]; bi = i; }
        bool sel[K_];
#pragma unroll
        for (int i = 0; i < K_; i++) sel[i] = false;
        sel[bi] = true;

        int n = n_exp[b];
        for (int t = 1; t < K_; t++) {
            float dist[K_];
#pragma unroll
            for (int i = 0; i < K_; i++) {
                if (sel[i]) dist[i] = -INFINITY;
                else {
                    float ms = -INFINITY;
#pragma unroll
                    for (int j = 0; j < K_; j++)
                        if (sel[j]) ms = fmaxf(ms, Smat[i][j]);
                    dist[i] = 1.0f - ms;
                }
            }
            int ai = 0; float av = dist[0];
#pragma unroll
            for (int i = 1; i < K_; i++) if (dist[i] > av) { av = dist[i]; ai = i; }
            if (t < n) sel[ai] = true;
        }

        float gl[K_], gm = -INFINITY;
#pragma unroll
        for (int i = 0; i < K_; i++) {
            gl[i] = (sel[i] ? conf[i] : NEGV) / TEMPV;
            gm = fmaxf(gm, gl[i]);
        }
        float gs = 0.0f;
#pragma unroll
        for (int i = 0; i < K_; i++) { gl[i] = __expf(gl[i] - gm); gs += gl[i]; }
#pragma unroll
        for (int i = 0; i < K_; i++) sgate[i] = gl[i] / gs;
    }
    __syncthreads();

    for (int c = tid; c < C_; c += 256) {
        float v = 0.0f;
#pragma unroll
        for (int k = 0; k < K_; k++) v += sgate[k] * sl[k * C_ + c];
        out_logits[(size_t)b * C_ + c] = v;
    }
    if (tid < K_) out_gates[(size_t)b * K_ + tid] = sgate[tid];
}

// ---------------------------------------------------------------------------
extern "C" void kernel_launch(void* const* d_in, const int* in_sizes, int n_in,
                              void* d_out, int out_size)
{
    const float* z    = (const float*)d_in[0];
    const int*   nexp = (const int*)d_in[1];
    const float* W1   = (const float*)d_in[2];
    const float* b1   = (const float*)d_in[3];
    const float* W2   = (const float*)d_in[4];
    const float* b2   = (const float*)d_in[5];
    float* out = (float*)d_out;

    __nv_bfloat16 *z0, *z1, *z2, *w10, *w11, *w12, *w20, *w21, *w22, *h0, *h1, *h2;
    float* lg;
    cudaGetSymbolAddress((void**)&z0, g_z0);   cudaGetSymbolAddress((void**)&z1, g_z1);
    cudaGetSymbolAddress((void**)&z2, g_z2);
    cudaGetSymbolAddress((void**)&w10, g_w1t0); cudaGetSymbolAddress((void**)&w11, g_w1t1);
    cudaGetSymbolAddress((void**)&w12, g_w1t2);
    cudaGetSymbolAddress((void**)&w20, g_w2t0); cudaGetSymbolAddress((void**)&w21, g_w2t1);
    cudaGetSymbolAddress((void**)&w22, g_w2t2);
    cudaGetSymbolAddress((void**)&h0, g_h0);   cudaGetSymbolAddress((void**)&h1, g_h1);
    cudaGetSymbolAddress((void**)&h2, g_h2);
    cudaGetSymbolAddress((void**)&lg, g_logits);

    cudaFuncSetAttribute(tc_gemm<true>,  cudaFuncAttributeMaxDynamicSharedMemorySize, 2 * STAGE_B);
    cudaFuncSetAttribute(tc_gemm<false>, cudaFuncAttributeMaxDynamicSharedMemorySize, 2 * STAGE_B);
    cudaFuncSetAttribute(gating_kernel,  cudaFuncAttributeMaxDynamicSharedMemorySize, 65536);

    // input conversions
    split3_kernel<<<(B_ * D_ + 255) / 256, 256>>>(z, z0, z1, z2, B_ * D_);
    trsplit_kernel<<<dim3(D_ / 32, D_ / 32, K_), dim3(32, 8)>>>(W1, w10, w11, w12, D_, D_);
    trsplit_kernel<<<dim3(CP_ / 32, D_ / 32, K_), dim3(32, 8)>>>(W2, w20, w21, w22, C_, CP_);

    // GEMM1: h = relu(z @ W1 + b1), re-split into 3 bf16 limbs
    tc_gemm<true><<<dim3(D_ / 128, B_ / 128, K_), 256, 2 * STAGE_B>>>(
        z0, z1, z2, 0LL,
        w10, w11, w12, (long long)D_ * D_,
        b1, D_, D_, nullptr, 0, h0, h1, h2);

    // GEMM2: logits = h @ W2 + b2 (fp32, padded to CP_)
    tc_gemm<false><<<dim3(CP_ / 128, B_ / 128, K_), 256, 2 * STAGE_B>>>(
        h0, h1, h2, (long long)B_ * D_,
        w20, w21, w22, (long long)CP_ * D_,
        b2, C_, C_, lg, CP_, nullptr, nullptr, nullptr);

    // gating + combine
    gating_kernel<<<B_, 256, 2 * K_ * C_ * sizeof(float)>>>(
        nexp, out, out + (size_t)B_ * C_);
}

// round 5
// speedup vs baseline: 2.0212x; 1.4691x over previous
#include <cuda_runtime.h>
#include <cuda_fp16.h>
#include <cstdint>
#include <math.h>

#define B_ 8192
#define D_ 512
#define C_ 1000
#define CP_ 1024
#define K_ 8
#define EPSV 1e-8f
#define TEMPV 0.2f
#define NEGV -10000.0f

// ---------------------------------------------------------------------------
// Scratch (__device__ globals)
// ---------------------------------------------------------------------------
__device__ __half g_z0[(size_t)B_ * D_];
__device__ __half g_z1[(size_t)B_ * D_];
__device__ __half g_w1t0[(size_t)K_ * D_ * D_];
__device__ __half g_w1t1[(size_t)K_ * D_ * D_];
__device__ __half g_w2t0[(size_t)K_ * CP_ * D_];
__device__ __half g_w2t1[(size_t)K_ * CP_ * D_];
__device__ __half g_h0[(size_t)K_ * B_ * D_];
__device__ __half g_h1[(size_t)K_ * B_ * D_];
__device__ float g_logits[(size_t)B_ * K_ * CP_];

// ---------------------------------------------------------------------------
// PTX helpers
// ---------------------------------------------------------------------------
__device__ __forceinline__ uint32_t smem_u32(const void* p) {
    uint32_t a;
    asm("{ .reg .u64 t; cvta.to.shared.u64 t, %1; cvt.u32.u64 %0, t; }" : "=r"(a) : "l"(p));
    return a;
}
__device__ __forceinline__ void cp_async16(uint32_t s, const void* g) {
    asm volatile("cp.async.cg.shared.global [%0], [%1], 16;" :: "r"(s), "l"(g));
}
__device__ __forceinline__ void cp_commit() { asm volatile("cp.async.commit_group;"); }
template <int N>
__device__ __forceinline__ void cp_wait() { asm volatile("cp.async.wait_group %0;" :: "n"(N)); }

__device__ __forceinline__ void ldsm4(uint32_t* r, uint32_t addr) {
    asm volatile("ldmatrix.sync.aligned.m8n8.x4.shared.b16 {%0,%1,%2,%3}, [%4];"
                 : "=r"(r[0]), "=r"(r[1]), "=r"(r[2]), "=r"(r[3]) : "r"(addr));
}
__device__ __forceinline__ void mma16816(float* c, const uint32_t* a, uint32_t b0, uint32_t b1) {
    asm volatile(
        "mma.sync.aligned.m16n8k16.row.col.f32.f16.f16.f32 "
        "{%0,%1,%2,%3}, {%4,%5,%6,%7}, {%8,%9}, {%0,%1,%2,%3};"
        : "+f"(c[0]), "+f"(c[1]), "+f"(c[2]), "+f"(c[3])
        : "r"(a[0]), "r"(a[1]), "r"(a[2]), "r"(a[3]), "r"(b0), "r"(b1));
}

// 2-limb fp16 split: x = a + b + O(2^-22 |x|)
__device__ __forceinline__ void split2(float x, __half& a, __half& b) {
    a = __float2half_rn(x);
    b = __float2half_rn(x - __half2float(a));
}

// ---------------------------------------------------------------------------
// Conversion kernels
// ---------------------------------------------------------------------------
__global__ void split2_kernel(const float* __restrict__ x, __half* __restrict__ o0,
                              __half* __restrict__ o1, int n) {
    int i = blockIdx.x * blockDim.x + threadIdx.x;
    if (i < n) split2(x[i], o0[i], o1[i]);
}

// in: [K][D_][Nin] fp32 -> out: [K][Npad][D_] fp16 x2 (transposed, rows >= Nin zeroed)
__global__ void trsplit_kernel(const float* __restrict__ in, __half* __restrict__ o0,
                               __half* __restrict__ o1, int Nin, int Npad) {
    __shared__ float t[32][33];
    const int k = blockIdx.z;
    const int n0 = blockIdx.x * 32, d0 = blockIdx.y * 32;
    const int tx = threadIdx.x, ty = threadIdx.y;
    const float* src = in + (size_t)k * D_ * Nin;
#pragma unroll
    for (int r = 0; r < 4; r++) {
        int d = d0 + ty + r * 8, n = n0 + tx;
        t[ty + r * 8][tx] = (n < Nin) ? src[(size_t)d * Nin + n] : 0.0f;
    }
    __syncthreads();
    size_t obase = (size_t)k * Npad * D_;
#pragma unroll
    for (int r = 0; r < 4; r++) {
        int nl = ty + r * 8;
        float v = t[tx][nl];
        __half a, b;
        split2(v, a, b);
        size_t oi = obase + (size_t)(n0 + nl) * D_ + d0 + tx;
        o0[oi] = a; o1[oi] = b;
    }
}

// ---------------------------------------------------------------------------
// HMMA fp16 GEMM with 3-product 2-limb split.
// Block 128x128, BK=32, 256 threads (8 warps: 2x4), warp tile 64x32.
// 3-stage cp.async pipeline. Both GEMMs have Kd = 512.
// ---------------------------------------------------------------------------
#define SPAD 40                      // smem row stride in fp16 (80B)
#define TILE_B (128 * SPAD * 2)      // 10240 B per limb tile
#define STAGE_B (4 * TILE_B)         // 40960 B (A0,A1,B0,B1)
#define NSTAGE 3
#define NCHUNK 16                    // 512 / 32

template <bool SPLIT>
__global__ void __launch_bounds__(256, 1) tc_gemm(
    const __half* __restrict__ A0, const __half* __restrict__ A1, long long aStr,
    const __half* __restrict__ B0, const __half* __restrict__ B1, long long bStr,
    const float* __restrict__ bias, int biasStr, int Nreal,
    float* __restrict__ outF, int outLd,
    __half* __restrict__ O0, __half* __restrict__ O1)
{
    extern __shared__ __align__(16) char dsm[];
    const uint32_t sbase = smem_u32(dsm);

    const int tid = threadIdx.x;
    const int warp = tid >> 5, lane = tid & 31;
    const int bz = blockIdx.z;
    const int m0 = blockIdx.y * 128, n0 = blockIdx.x * 128;
    const int warpM = (warp >> 2) * 64;   // 0 or 64
    const int warpN = (warp & 3) * 32;    // 0,32,64,96

    const char* gp[4];
    gp[0] = (const char*)A0 + ((size_t)bz * aStr + (size_t)m0 * D_) * 2;
    gp[1] = (const char*)A1 + ((size_t)bz * aStr + (size_t)m0 * D_) * 2;
    gp[2] = (const char*)B0 + ((size_t)bz * bStr + (size_t)n0 * D_) * 2;
    gp[3] = (const char*)B1 + ((size_t)bz * bStr + (size_t)n0 * D_) * 2;

    auto load_stage = [&](int kk, int buf) {
#pragma unroll
        for (int t = 0; t < 4; t++) {
            uint32_t sb = sbase + buf * STAGE_B + t * TILE_B;
            const char* g = gp[t] + (size_t)kk * 64;   // 32 fp16 = 64B chunk
#pragma unroll
            for (int i = 0; i < 2; i++) {
                int idx = tid + i * 256;
                int row = idx >> 2, c = idx & 3;
                cp_async16(sb + row * 80 + c * 16, g + (size_t)row * 1024 + c * 16);
            }
        }
        cp_commit();
    };

    float acc[4][4][4];
#pragma unroll
    for (int i = 0; i < 4; i++)
#pragma unroll
        for (int j = 0; j < 4; j++)
#pragma unroll
            for (int r = 0; r < 4; r++) acc[i][j][r] = 0.0f;

    load_stage(0, 0);
    load_stage(1, 1);

    // products: a0b0, a0b1, a1b0 (a1b1 dropped: ~2^-22)
    constexpr int LA[3] = {0, 0, 1};
    constexpr int LB[3] = {0, 1, 0};

    for (int kk = 0; kk < NCHUNK; kk++) {
        const int buf = kk % NSTAGE;
        if (kk == NCHUNK - 1) cp_wait<0>(); else cp_wait<1>();
        __syncthreads();
        if (kk + 2 < NCHUNK) load_stage(kk + 2, (kk + 2) % NSTAGE);

        const uint32_t sb = sbase + buf * STAGE_B;
        const uint32_t aRowOff = (uint32_t)(warpM + (lane & 15)) * 80 + (lane >> 4) * 16;
        const uint32_t bRowOff = (uint32_t)(warpN + (lane & 7) + ((lane >> 4) & 1) * 8) * 80 +
                                 ((lane >> 3) & 1) * 16;

#pragma unroll
        for (int ks = 0; ks < 2; ks++) {
            uint32_t afr[2][4][4];   // [limb][mfrag][reg]
            uint32_t bfr[2][2][4];   // [limb][jpair][reg]
#pragma unroll
            for (int p = 0; p < 2; p++) {
#pragma unroll
                for (int i = 0; i < 4; i++)
                    ldsm4(afr[p][i], sb + p * TILE_B + aRowOff + i * 16 * 80 + ks * 32);
#pragma unroll
                for (int jp = 0; jp < 2; jp++)
                    ldsm4(bfr[p][jp], sb + (2 + p) * TILE_B + bRowOff + jp * 16 * 80 + ks * 32);
            }
#pragma unroll
            for (int p = 0; p < 3; p++) {
#pragma unroll
                for (int i = 0; i < 4; i++)
#pragma unroll
                    for (int j = 0; j < 4; j++)
                        mma16816(acc[i][j], afr[LA[p]][i],
                                 bfr[LB[p]][j >> 1][(j & 1) * 2],
                                 bfr[LB[p]][j >> 1][(j & 1) * 2 + 1]);
            }
        }
    }

    // ---------------- epilogue ----------------
    const int mBase = m0 + warpM + (lane >> 2);
    const int nBase = n0 + warpN + (lane & 3) * 2;
#pragma unroll
    for (int i = 0; i < 4; i++) {
#pragma unroll
        for (int j = 0; j < 4; j++) {
#pragma unroll
            for (int half = 0; half < 2; half++) {
                const int m = mBase + i * 16 + half * 8;
                const int n = nBase + j * 8;
                float v0 = acc[i][j][half * 2];
                float v1 = acc[i][j][half * 2 + 1];
                if (SPLIT) {
                    v0 = fmaxf(v0 + bias[bz * biasStr + n], 0.0f);
                    v1 = fmaxf(v1 + bias[bz * biasStr + n + 1], 0.0f);
                    __half a0, b0, a1, b1;
                    split2(v0, a0, b0);
                    split2(v1, a1, b1);
                    size_t ob = ((size_t)bz * B_ + m) * D_ + n;
                    *(__half2*)&O0[ob] = __half2(a0, a1);
                    *(__half2*)&O1[ob] = __half2(b0, b1);
                } else {
                    if (n < Nreal) {
                        v0 += bias[bz * biasStr + n];
                        v1 += bias[bz * biasStr + n + 1];
                    }
                    float2 vv = make_float2(v0, v1);
                    *(float2*)&outF[((size_t)m * K_ + bz) * outLd + n] = vv;
                }
            }
        }
    }
}

// ---------------------------------------------------------------------------
// Gating kernel (logits strided [b][k][CP_])
// ---------------------------------------------------------------------------
__global__ void __launch_bounds__(256) gating_kernel(
    const int* __restrict__ n_exp,
    float* __restrict__ out_logits,
    float* __restrict__ out_gates)
{
    extern __shared__ float sm[];
    float* sl = sm;             // [K_*C_]
    float* se = sm + K_ * C_;   // [K_*C_]
    __shared__ float sZ[K_], sG[K_ * K_], sgate[K_];

    const int b = blockIdx.x, tid = threadIdx.x;
    const int w = tid >> 5, lane = tid & 31;

    const float* lrow = g_logits + (size_t)b * K_ * CP_;
    for (int i = tid; i < K_ * C_; i += 256) {
        int k = i / C_, c = i - k * C_;
        sl[i] = lrow[(size_t)k * CP_ + c];
    }
    __syncthreads();

    {
        float m = -INFINITY;
        for (int c = lane; c < C_; c += 32) m = fmaxf(m, sl[w * C_ + c]);
#pragma unroll
        for (int o = 16; o > 0; o >>= 1) m = fmaxf(m, __shfl_xor_sync(0xffffffffu, m, o));
        float z = 0.0f;
        for (int c = lane; c < C_; c += 32) {
            float e = __expf(sl[w * C_ + c] - m);
            se[w * C_ + c] = e;
            z += e;
        }
#pragma unroll
        for (int o = 16; o > 0; o >>= 1) z += __shfl_xor_sync(0xffffffffu, z, o);
        if (lane == 0) sZ[w] = z;
    }
    __syncthreads();

    for (int p = w; p < 36; p += 8) {
        int i = 0, q = p;
        while (q >= K_ - i) { q -= (K_ - i); i++; }
        int j = i + q;
        float s = 0.0f;
        for (int c = lane; c < C_; c += 32) s += se[i * C_ + c] * se[j * C_ + c];
#pragma unroll
        for (int o = 16; o > 0; o >>= 1) s += __shfl_xor_sync(0xffffffffu, s, o);
        if (lane == 0) {
            float g = s / (sZ[i] * sZ[j]);
            sG[i * K_ + j] = g;
            sG[j * K_ + i] = g;
        }
    }
    __syncthreads();

    if (tid == 0) {
        float Smat[K_][K_], conf[K_], nrm[K_];
#pragma unroll
        for (int i = 0; i < K_; i++) {
            nrm[i] = sqrtf(sG[i * K_ + i]) + EPSV;
            conf[i] = 1.0f / sZ[i];
        }
#pragma unroll
        for (int i = 0; i < K_; i++)
#pragma unroll
            for (int j = 0; j < K_; j++)
                Smat[i][j] = sG[i * K_ + j] / (nrm[i] * nrm[j]);

        int bi = 0; float bv = conf[0];
#pragma unroll
        for (int i = 1; i < K_; i++) if (conf[i] > bv) { bv = conf[i]; bi = i; }
        bool sel[K_];
#pragma unroll
        for (int i = 0; i < K_; i++) sel[i] = false;
        sel[bi] = true;

        int n = n_exp[b];
        for (int t = 1; t < K_; t++) {
            float dist[K_];
#pragma unroll
            for (int i = 0; i < K_; i++) {
                if (sel[i]) dist[i] = -INFINITY;
                else {
                    float ms = -INFINITY;
#pragma unroll
                    for (int j = 0; j < K_; j++)
                        if (sel[j]) ms = fmaxf(ms, Smat[i][j]);
                    dist[i] = 1.0f - ms;
                }
            }
            int ai = 0; float av = dist[0];
#pragma unroll
            for (int i = 1; i < K_; i++) if (dist[i] > av) { av = dist[i]; ai = i; }
            if (t < n) sel[ai] = true;
        }

        float gl[K_], gm = -INFINITY;
#pragma unroll
        for (int i = 0; i < K_; i++) {
            gl[i] = (sel[i] ? conf[i] : NEGV) / TEMPV;
            gm = fmaxf(gm, gl[i]);
        }
        float gs = 0.0f;
#pragma unroll
        for (int i = 0; i < K_; i++) { gl[i] = __expf(gl[i] - gm); gs += gl[i]; }
#pragma unroll
        for (int i = 0; i < K_; i++) sgate[i] = gl[i] / gs;
    }
    __syncthreads();

    for (int c = tid; c < C_; c += 256) {
        float v = 0.0f;
#pragma unroll
        for (int k = 0; k < K_; k++) v += sgate[k] * sl[k * C_ + c];
        out_logits[(size_t)b * C_ + c] = v;
    }
    if (tid < K_) out_gates[(size_t)b * K_ + tid] = sgate[tid];
}

// ---------------------------------------------------------------------------
extern "C" void kernel_launch(void* const* d_in, const int* in_sizes, int n_in,
                              void* d_out, int out_size)
{
    const float* z    = (const float*)d_in[0];
    const int*   nexp = (const int*)d_in[1];
    const float* W1   = (const float*)d_in[2];
    const float* b1   = (const float*)d_in[3];
    const float* W2   = (const float*)d_in[4];
    const float* b2   = (const float*)d_in[5];
    float* out = (float*)d_out;

    __half *z0, *z1, *w10, *w11, *w20, *w21, *h0, *h1;
    float* lg;
    cudaGetSymbolAddress((void**)&z0, g_z0);   cudaGetSymbolAddress((void**)&z1, g_z1);
    cudaGetSymbolAddress((void**)&w10, g_w1t0); cudaGetSymbolAddress((void**)&w11, g_w1t1);
    cudaGetSymbolAddress((void**)&w20, g_w2t0); cudaGetSymbolAddress((void**)&w21, g_w2t1);
    cudaGetSymbolAddress((void**)&h0, g_h0);   cudaGetSymbolAddress((void**)&h1, g_h1);
    cudaGetSymbolAddress((void**)&lg, g_logits);

    cudaFuncSetAttribute(tc_gemm<true>,  cudaFuncAttributeMaxDynamicSharedMemorySize, NSTAGE * STAGE_B);
    cudaFuncSetAttribute(tc_gemm<false>, cudaFuncAttributeMaxDynamicSharedMemorySize, NSTAGE * STAGE_B);
    cudaFuncSetAttribute(gating_kernel,  cudaFuncAttributeMaxDynamicSharedMemorySize, 65536);

    // input conversions
    split2_kernel<<<(B_ * D_ + 255) / 256, 256>>>(z, z0, z1, B_ * D_);
    trsplit_kernel<<<dim3(D_ / 32, D_ / 32, K_), dim3(32, 8)>>>(W1, w10, w11, D_, D_);
    trsplit_kernel<<<dim3(CP_ / 32, D_ / 32, K_), dim3(32, 8)>>>(W2, w20, w21, C_, CP_);

    // GEMM1: h = relu(z @ W1 + b1), re-split into 2 fp16 limbs
    tc_gemm<true><<<dim3(D_ / 128, B_ / 128, K_), 256, NSTAGE * STAGE_B>>>(
        z0, z1, 0LL,
        w10, w11, (long long)D_ * D_,
        b1, D_, D_, nullptr, 0, h0, h1);

    // GEMM2: logits = h @ W2 + b2 (fp32, padded to CP_)
    tc_gemm<false><<<dim3(CP_ / 128, B_ / 128, K_), 256, NSTAGE * STAGE_B>>>(
        h0, h1, (long long)B_ * D_,
        w20, w21, (long long)CP_ * D_,
        b2, C_, C_, lg, CP_, nullptr, nullptr);

    // gating + combine
    gating_kernel<<<B_, 256, 2 * K_ * C_ * sizeof(float)>>>(
        nexp, out, out + (size_t)B_ * C_);
}

// round 6
// speedup vs baseline: 2.2703x; 1.1232x over previous
#include <cuda_runtime.h>
#include <cuda_fp16.h>
#include <cstdint>
#include <math.h>

#define B_ 8192
#define D_ 512
#define C_ 1000
#define CP_ 1024
#define K_ 8
#define EPSV 1e-8f
#define TEMPV 0.2f
#define NEGV -10000.0f

// ---------------------------------------------------------------------------
// Scratch (__device__ globals)
// ---------------------------------------------------------------------------
__device__ __half g_z0[(size_t)B_ * D_];
__device__ __half g_z1[(size_t)B_ * D_];
__device__ __half g_w1t0[(size_t)K_ * D_ * D_];
__device__ __half g_w1t1[(size_t)K_ * D_ * D_];
__device__ __half g_w2t0[(size_t)K_ * CP_ * D_];
__device__ __half g_w2t1[(size_t)K_ * CP_ * D_];
__device__ __half g_h0[(size_t)K_ * B_ * D_];
__device__ __half g_h1[(size_t)K_ * B_ * D_];
__device__ float g_logits[(size_t)B_ * K_ * CP_];

// ---------------------------------------------------------------------------
// PTX helpers
// ---------------------------------------------------------------------------
__device__ __forceinline__ uint32_t smem_u32(const void* p) {
    uint32_t a;
    asm("{ .reg .u64 t; cvta.to.shared.u64 t, %1; cvt.u32.u64 %0, t; }" : "=r"(a) : "l"(p));
    return a;
}
__device__ __forceinline__ void cp_async16(uint32_t s, const void* g) {
    asm volatile("cp.async.cg.shared.global [%0], [%1], 16;" :: "r"(s), "l"(g));
}
__device__ __forceinline__ void cp_commit() { asm volatile("cp.async.commit_group;"); }
template <int N>
__device__ __forceinline__ void cp_wait() { asm volatile("cp.async.wait_group %0;" :: "n"(N)); }

__device__ __forceinline__ void ldsm4(uint32_t* r, uint32_t addr) {
    asm volatile("ldmatrix.sync.aligned.m8n8.x4.shared.b16 {%0,%1,%2,%3}, [%4];"
                 : "=r"(r[0]), "=r"(r[1]), "=r"(r[2]), "=r"(r[3]) : "r"(addr));
}
__device__ __forceinline__ void mma16816(float* c, const uint32_t* a, uint32_t b0, uint32_t b1) {
    asm volatile(
        "mma.sync.aligned.m16n8k16.row.col.f32.f16.f16.f32 "
        "{%0,%1,%2,%3}, {%4,%5,%6,%7}, {%8,%9}, {%0,%1,%2,%3};"
        : "+f"(c[0]), "+f"(c[1]), "+f"(c[2]), "+f"(c[3])
        : "r"(a[0]), "r"(a[1]), "r"(a[2]), "r"(a[3]), "r"(b0), "r"(b1));
}

// 2-limb fp16 split: x = a + b + O(2^-22 |x|)
__device__ __forceinline__ void split2(float x, __half& a, __half& b) {
    a = __float2half_rn(x);
    b = __float2half_rn(x - __half2float(a));
}

// ---------------------------------------------------------------------------
// Conversion kernels
// ---------------------------------------------------------------------------
__global__ void split2_kernel(const float* __restrict__ x, __half* __restrict__ o0,
                              __half* __restrict__ o1, int n) {
    int i = blockIdx.x * blockDim.x + threadIdx.x;
    if (i < n) split2(x[i], o0[i], o1[i]);
}

// in: [K][D_][Nin] fp32 -> out: [K][Npad][D_] fp16 x2 (transposed, rows >= Nin zeroed)
__global__ void trsplit_kernel(const float* __restrict__ in, __half* __restrict__ o0,
                               __half* __restrict__ o1, int Nin, int Npad) {
    __shared__ float t[32][33];
    const int k = blockIdx.z;
    const int n0 = blockIdx.x * 32, d0 = blockIdx.y * 32;
    const int tx = threadIdx.x, ty = threadIdx.y;
    const float* src = in + (size_t)k * D_ * Nin;
#pragma unroll
    for (int r = 0; r < 4; r++) {
        int d = d0 + ty + r * 8, n = n0 + tx;
        t[ty + r * 8][tx] = (n < Nin) ? src[(size_t)d * Nin + n] : 0.0f;
    }
    __syncthreads();
    size_t obase = (size_t)k * Npad * D_;
#pragma unroll
    for (int r = 0; r < 4; r++) {
        int nl = ty + r * 8;
        float v = t[tx][nl];
        __half a, b;
        split2(v, a, b);
        size_t oi = obase + (size_t)(n0 + nl) * D_ + d0 + tx;
        o0[oi] = a; o1[oi] = b;
    }
}

// ---------------------------------------------------------------------------
// HMMA fp16 GEMM with 3-product 2-limb split.
// Block 128x128, BK=32, 256 threads (8 warps: 2x4), warp tile 64x32.
// 2-stage cp.async pipeline, 2 CTAs/SM. Both GEMMs have Kd = 512.
// ---------------------------------------------------------------------------
#define SPAD 40                      // smem row stride in fp16 (80B)
#define TILE_B (128 * SPAD * 2)      // 10240 B per limb tile
#define STAGE_B (4 * TILE_B)         // 40960 B (A0,A1,B0,B1)
#define NSTAGE 2
#define NCHUNK 16                    // 512 / 32

template <bool SPLIT>
__global__ void __launch_bounds__(256, 2) tc_gemm(
    const __half* __restrict__ A0, const __half* __restrict__ A1, long long aStr,
    const __half* __restrict__ B0, const __half* __restrict__ B1, long long bStr,
    const float* __restrict__ bias, int biasStr, int Nreal,
    float* __restrict__ outF, int outLd,
    __half* __restrict__ O0, __half* __restrict__ O1)
{
    extern __shared__ __align__(16) char dsm[];
    const uint32_t sbase = smem_u32(dsm);

    const int tid = threadIdx.x;
    const int warp = tid >> 5, lane = tid & 31;
    const int bz = blockIdx.z;
    const int m0 = blockIdx.y * 128, n0 = blockIdx.x * 128;
    const int warpM = (warp >> 2) * 64;   // 0 or 64
    const int warpN = (warp & 3) * 32;    // 0,32,64,96

    const char* gp[4];
    gp[0] = (const char*)A0 + ((size_t)bz * aStr + (size_t)m0 * D_) * 2;
    gp[1] = (const char*)A1 + ((size_t)bz * aStr + (size_t)m0 * D_) * 2;
    gp[2] = (const char*)B0 + ((size_t)bz * bStr + (size_t)n0 * D_) * 2;
    gp[3] = (const char*)B1 + ((size_t)bz * bStr + (size_t)n0 * D_) * 2;

    auto load_stage = [&](int kk, int buf) {
#pragma unroll
        for (int t = 0; t < 4; t++) {
            uint32_t sb = sbase + buf * STAGE_B + t * TILE_B;
            const char* g = gp[t] + (size_t)kk * 64;   // 32 fp16 = 64B chunk
#pragma unroll
            for (int i = 0; i < 2; i++) {
                int idx = tid + i * 256;
                int row = idx >> 2, c = idx & 3;
                cp_async16(sb + row * 80 + c * 16, g + (size_t)row * 1024 + c * 16);
            }
        }
        cp_commit();
    };

    float acc[4][4][4];
#pragma unroll
    for (int i = 0; i < 4; i++)
#pragma unroll
        for (int j = 0; j < 4; j++)
#pragma unroll
            for (int r = 0; r < 4; r++) acc[i][j][r] = 0.0f;

    load_stage(0, 0);
    load_stage(1, 1);

    for (int kk = 0; kk < NCHUNK; kk++) {
        const int buf = kk & 1;
        if (kk == NCHUNK - 1) cp_wait<0>(); else cp_wait<1>();
        __syncthreads();

        const uint32_t sb = sbase + buf * STAGE_B;
        const uint32_t aRowOff = (uint32_t)(warpM + (lane & 15)) * 80 + (lane >> 4) * 16;
        const uint32_t bRowOff = (uint32_t)(warpN + (lane & 7) + ((lane >> 4) & 1) * 8) * 80 +
                                 ((lane >> 3) & 1) * 16;

#pragma unroll
        for (int ks = 0; ks < 2; ks++) {
            // ordered to minimize live fragment registers:
            // a0,b0 -> a0b0 ; b1 -> a0b1 (drop b1,a0) ; a1 -> a1b0
            uint32_t a0f[4][4], b0f[2][4];
#pragma unroll
            for (int i = 0; i < 4; i++)
                ldsm4(a0f[i], sb + 0 * TILE_B + aRowOff + i * 16 * 80 + ks * 32);
#pragma unroll
            for (int jp = 0; jp < 2; jp++)
                ldsm4(b0f[jp], sb + 2 * TILE_B + bRowOff + jp * 16 * 80 + ks * 32);
#pragma unroll
            for (int i = 0; i < 4; i++)
#pragma unroll
                for (int j = 0; j < 4; j++)
                    mma16816(acc[i][j], a0f[i], b0f[j >> 1][(j & 1) * 2],
                             b0f[j >> 1][(j & 1) * 2 + 1]);
            {
                uint32_t b1f[2][4];
#pragma unroll
                for (int jp = 0; jp < 2; jp++)
                    ldsm4(b1f[jp], sb + 3 * TILE_B + bRowOff + jp * 16 * 80 + ks * 32);
#pragma unroll
                for (int i = 0; i < 4; i++)
#pragma unroll
                    for (int j = 0; j < 4; j++)
                        mma16816(acc[i][j], a0f[i], b1f[j >> 1][(j & 1) * 2],
                                 b1f[j >> 1][(j & 1) * 2 + 1]);
            }
            {
                uint32_t a1f[4][4];
#pragma unroll
                for (int i = 0; i < 4; i++)
                    ldsm4(a1f[i], sb + 1 * TILE_B + aRowOff + i * 16 * 80 + ks * 32);
#pragma unroll
                for (int i = 0; i < 4; i++)
#pragma unroll
                    for (int j = 0; j < 4; j++)
                        mma16816(acc[i][j], a1f[i], b0f[j >> 1][(j & 1) * 2],
                                 b0f[j >> 1][(j & 1) * 2 + 1]);
            }
        }
        __syncthreads();
        if (kk + 2 < NCHUNK) load_stage(kk + 2, buf);
    }

    // ---------------- epilogue ----------------
    const int mBase = m0 + warpM + (lane >> 2);
    const int nBase = n0 + warpN + (lane & 3) * 2;
#pragma unroll
    for (int i = 0; i < 4; i++) {
#pragma unroll
        for (int j = 0; j < 4; j++) {
#pragma unroll
            for (int half = 0; half < 2; half++) {
                const int m = mBase + i * 16 + half * 8;
                const int n = nBase + j * 8;
                float v0 = acc[i][j][half * 2];
                float v1 = acc[i][j][half * 2 + 1];
                if (SPLIT) {
                    v0 = fmaxf(v0 + bias[bz * biasStr + n], 0.0f);
                    v1 = fmaxf(v1 + bias[bz * biasStr + n + 1], 0.0f);
                    __half a0, b0, a1, b1;
                    split2(v0, a0, b0);
                    split2(v1, a1, b1);
                    size_t ob = ((size_t)bz * B_ + m) * D_ + n;
                    *(__half2*)&O0[ob] = __half2(a0, a1);
                    *(__half2*)&O1[ob] = __half2(b0, b1);
                } else {
                    if (n < Nreal) {
                        v0 += bias[bz * biasStr + n];
                        v1 += bias[bz * biasStr + n + 1];
                    }
                    float2 vv = make_float2(v0, v1);
                    *(float2*)&outF[((size_t)m * K_ + bz) * outLd + n] = vv;
                }
            }
        }
    }
}

// ---------------------------------------------------------------------------
// Gating kernel (logits strided [b][k][CP_])
// ---------------------------------------------------------------------------
__global__ void __launch_bounds__(256) gating_kernel(
    const int* __restrict__ n_exp,
    float* __restrict__ out_logits,
    float* __restrict__ out_gates)
{
    extern __shared__ float sm[];
    float* sl = sm;             // [K_*C_]
    float* se = sm + K_ * C_;   // [K_*C_]
    __shared__ float sZ[K_], sG[K_ * K_], sgate[K_];

    const int b = blockIdx.x, tid = threadIdx.x;
    const int w = tid >> 5, lane = tid & 31;

    const float* lrow = g_logits + (size_t)b * K_ * CP_;
    for (int i = tid; i < K_ * C_; i += 256) {
        int k = i / C_, c = i - k * C_;
        sl[i] = lrow[(size_t)k * CP_ + c];
    }
    __syncthreads();

    {
        float m = -INFINITY;
        for (int c = lane; c < C_; c += 32) m = fmaxf(m, sl[w * C_ + c]);
#pragma unroll
        for (int o = 16; o > 0; o >>= 1) m = fmaxf(m, __shfl_xor_sync(0xffffffffu, m, o));
        float z = 0.0f;
        for (int c = lane; c < C_; c += 32) {
            float e = __expf(sl[w * C_ + c] - m);
            se[w * C_ + c] = e;
            z += e;
        }
#pragma unroll
        for (int o = 16; o > 0; o >>= 1) z += __shfl_xor_sync(0xffffffffu, z, o);
        if (lane == 0) sZ[w] = z;
    }
    __syncthreads();

    for (int p = w; p < 36; p += 8) {
        int i = 0, q = p;
        while (q >= K_ - i) { q -= (K_ - i); i++; }
        int j = i + q;
        float s = 0.0f;
        for (int c = lane; c < C_; c += 32) s += se[i * C_ + c] * se[j * C_ + c];
#pragma unroll
        for (int o = 16; o > 0; o >>= 1) s += __shfl_xor_sync(0xffffffffu, s, o);
        if (lane == 0) {
            float g = s / (sZ[i] * sZ[j]);
            sG[i * K_ + j] = g;
            sG[j * K_ + i] = g;
        }
    }
    __syncthreads();

    if (tid == 0) {
        float Smat[K_][K_], conf[K_], nrm[K_];
#pragma unroll
        for (int i = 0; i < K_; i++) {
            nrm[i] = sqrtf(sG[i * K_ + i]) + EPSV;
            conf[i] = 1.0f / sZ[i];
        }
#pragma unroll
        for (int i = 0; i < K_; i++)
#pragma unroll
            for (int j = 0; j < K_; j++)
                Smat[i][j] = sG[i * K_ + j] / (nrm[i] * nrm[j]);

        int bi = 0; float bv = conf[0];
#pragma unroll
        for (int i = 1; i < K_; i++) if (conf[i] > bv) { bv = conf[i]; bi = i; }
        bool sel[K_];
#pragma unroll
        for (int i = 0; i < K_; i++) sel[i] = false;
        sel[bi] = true;

        int n = n_exp[b];
        for (int t = 1; t < K_; t++) {
            float dist[K_];
#pragma unroll
            for (int i = 0; i < K_; i++) {
                if (sel[i]) dist[i] = -INFINITY;
                else {
                    float ms = -INFINITY;
#pragma unroll
                    for (int j = 0; j < K_; j++)
                        if (sel[j]) ms = fmaxf(ms, Smat[i][j]);
                    dist[i] = 1.0f - ms;
                }
            }
            int ai = 0; float av = dist[0];
#pragma unroll
            for (int i = 1; i < K_; i++) if (dist[i] > av) { av = dist[i]; ai = i; }
            if (t < n) sel[ai] = true;
        }

        float gl[K_], gm = -INFINITY;
#pragma unroll
        for (int i = 0; i < K_; i++) {
            gl[i] = (sel[i] ? conf[i] : NEGV) / TEMPV;
            gm = fmaxf(gm, gl[i]);
        }
        float gs = 0.0f;
#pragma unroll
        for (int i = 0; i < K_; i++) { gl[i] = __expf(gl[i] - gm); gs += gl[i]; }
#pragma unroll
        for (int i = 0; i < K_; i++) sgate[i] = gl[i] / gs;
    }
    __syncthreads();

    for (int c = tid; c < C_; c += 256) {
        float v = 0.0f;
#pragma unroll
        for (int k = 0; k < K_; k++) v += sgate[k] * sl[k * C_ + c];
        out_logits[(size_t)b * C_ + c] = v;
    }
    if (tid < K_) out_gates[(size_t)b * K_ + tid] = sgate[tid];
}

// ---------------------------------------------------------------------------
extern "C" void kernel_launch(void* const* d_in, const int* in_sizes, int n_in,
                              void* d_out, int out_size)
{
    const float* z    = (const float*)d_in[0];
    const int*   nexp = (const int*)d_in[1];
    const float* W1   = (const float*)d_in[2];
    const float* b1   = (const float*)d_in[3];
    const float* W2   = (const float*)d_in[4];
    const float* b2   = (const float*)d_in[5];
    float* out = (float*)d_out;

    __half *z0, *z1, *w10, *w11, *w20, *w21, *h0, *h1;
    float* lg;
    cudaGetSymbolAddress((void**)&z0, g_z0);   cudaGetSymbolAddress((void**)&z1, g_z1);
    cudaGetSymbolAddress((void**)&w10, g_w1t0); cudaGetSymbolAddress((void**)&w11, g_w1t1);
    cudaGetSymbolAddress((void**)&w20, g_w2t0); cudaGetSymbolAddress((void**)&w21, g_w2t1);
    cudaGetSymbolAddress((void**)&h0, g_h0);   cudaGetSymbolAddress((void**)&h1, g_h1);
    cudaGetSymbolAddress((void**)&lg, g_logits);

    cudaFuncSetAttribute(tc_gemm<true>,  cudaFuncAttributeMaxDynamicSharedMemorySize, NSTAGE * STAGE_B);
    cudaFuncSetAttribute(tc_gemm<false>, cudaFuncAttributeMaxDynamicSharedMemorySize, NSTAGE * STAGE_B);
    cudaFuncSetAttribute(gating_kernel,  cudaFuncAttributeMaxDynamicSharedMemorySize, 65536);

    // input conversions
    split2_kernel<<<(B_ * D_ + 255) / 256, 256>>>(z, z0, z1, B_ * D_);
    trsplit_kernel<<<dim3(D_ / 32, D_ / 32, K_), dim3(32, 8)>>>(W1, w10, w11, D_, D_);
    trsplit_kernel<<<dim3(CP_ / 32, D_ / 32, K_), dim3(32, 8)>>>(W2, w20, w21, C_, CP_);

    // GEMM1: h = relu(z @ W1 + b1), re-split into 2 fp16 limbs
    tc_gemm<true><<<dim3(D_ / 128, B_ / 128, K_), 256, NSTAGE * STAGE_B>>>(
        z0, z1, 0LL,
        w10, w11, (long long)D_ * D_,
        b1, D_, D_, nullptr, 0, h0, h1);

    // GEMM2: logits = h @ W2 + b2 (fp32, padded to CP_)
    tc_gemm<false><<<dim3(CP_ / 128, B_ / 128, K_), 256, NSTAGE * STAGE_B>>>(
        h0, h1, (long long)B_ * D_,
        w20, w21, (long long)CP_ * D_,
        b2, C_, C_, lg, CP_, nullptr, nullptr);

    // gating + combine
    gating_kernel<<<B_, 256, 2 * K_ * C_ * sizeof(float)>>>(
        nexp, out, out + (size_t)B_ * C_);
}

// round 7
// speedup vs baseline: 2.4662x; 1.0863x over previous
#include <cuda_runtime.h>
#include <cuda_fp16.h>
#include <cstdint>
#include <math.h>

#define B_ 8192
#define D_ 512
#define C_ 1000
#define CP_ 1024
#define K_ 8
#define EPSV 1e-8f
#define TEMPV 0.2f
#define NEGV -10000.0f

// ---------------------------------------------------------------------------
// Scratch (__device__ globals)
// ---------------------------------------------------------------------------
__device__ __half g_z0[(size_t)B_ * D_];
__device__ __half g_z1[(size_t)B_ * D_];
__device__ __half g_w1t0[(size_t)K_ * D_ * D_];
__device__ __half g_w1t1[(size_t)K_ * D_ * D_];
__device__ __half g_w2t0[(size_t)K_ * CP_ * D_];
__device__ __half g_w2t1[(size_t)K_ * CP_ * D_];
__device__ __half g_h0[(size_t)K_ * B_ * D_];
__device__ __half g_h1[(size_t)K_ * B_ * D_];
__device__ float g_logits[(size_t)B_ * K_ * CP_];

// ---------------------------------------------------------------------------
// PTX helpers
// ---------------------------------------------------------------------------
__device__ __forceinline__ uint32_t smem_u32(const void* p) {
    uint32_t a;
    asm("{ .reg .u64 t; cvta.to.shared.u64 t, %1; cvt.u32.u64 %0, t; }" : "=r"(a) : "l"(p));
    return a;
}
__device__ __forceinline__ void cp_async16(uint32_t s, const void* g) {
    asm volatile("cp.async.cg.shared.global [%0], [%1], 16;" :: "r"(s), "l"(g));
}
__device__ __forceinline__ void cp_commit() { asm volatile("cp.async.commit_group;"); }
template <int N>
__device__ __forceinline__ void cp_wait() { asm volatile("cp.async.wait_group %0;" :: "n"(N)); }

__device__ __forceinline__ void ldsm4(uint32_t* r, uint32_t addr) {
    asm volatile("ldmatrix.sync.aligned.m8n8.x4.shared.b16 {%0,%1,%2,%3}, [%4];"
                 : "=r"(r[0]), "=r"(r[1]), "=r"(r[2]), "=r"(r[3]) : "r"(addr));
}
__device__ __forceinline__ void mma16816(float* c, const uint32_t* a, uint32_t b0, uint32_t b1) {
    asm volatile(
        "mma.sync.aligned.m16n8k16.row.col.f32.f16.f16.f32 "
        "{%0,%1,%2,%3}, {%4,%5,%6,%7}, {%8,%9}, {%0,%1,%2,%3};"
        : "+f"(c[0]), "+f"(c[1]), "+f"(c[2]), "+f"(c[3])
        : "r"(a[0]), "r"(a[1]), "r"(a[2]), "r"(a[3]), "r"(b0), "r"(b1));
}

// 2-limb fp16 split: x = a + b + O(2^-22 |x|)
__device__ __forceinline__ void split2(float x, __half& a, __half& b) {
    a = __float2half_rn(x);
    b = __float2half_rn(x - __half2float(a));
}

// ---------------------------------------------------------------------------
// Conversion kernels
// ---------------------------------------------------------------------------
__global__ void split2_kernel(const float* __restrict__ x, __half* __restrict__ o0,
                              __half* __restrict__ o1, int n) {
    int i = blockIdx.x * blockDim.x + threadIdx.x;
    if (i < n) split2(x[i], o0[i], o1[i]);
}

// in: [K][D_][Nin] fp32 -> out: [K][Npad][D_] fp16 x2 (transposed, rows >= Nin zeroed)
__global__ void trsplit_kernel(const float* __restrict__ in, __half* __restrict__ o0,
                               __half* __restrict__ o1, int Nin, int Npad) {
    __shared__ float t[32][33];
    const int k = blockIdx.z;
    const int n0 = blockIdx.x * 32, d0 = blockIdx.y * 32;
    const int tx = threadIdx.x, ty = threadIdx.y;
    const float* src = in + (size_t)k * D_ * Nin;
#pragma unroll
    for (int r = 0; r < 4; r++) {
        int d = d0 + ty + r * 8, n = n0 + tx;
        t[ty + r * 8][tx] = (n < Nin) ? src[(size_t)d * Nin + n] : 0.0f;
    }
    __syncthreads();
    size_t obase = (size_t)k * Npad * D_;
#pragma unroll
    for (int r = 0; r < 4; r++) {
        int nl = ty + r * 8;
        float v = t[tx][nl];
        __half a, b;
        split2(v, a, b);
        size_t oi = obase + (size_t)(n0 + nl) * D_ + d0 + tx;
        o0[oi] = a; o1[oi] = b;
    }
}

// ---------------------------------------------------------------------------
// HMMA fp16 GEMM with 3-product 2-limb split.
// Block 128x128, BK=32, 256 threads (8 warps: 2x4), warp tile 64x32.
// 3-stage cp.async pipeline, XOR-swizzled packed smem, 2 CTAs/SM.
// smem layout per limb tile: 128 rows x 64B; addr = row*64 + ((c ^ ((row>>1)&3))<<4)
// ---------------------------------------------------------------------------
#define TILE_B 8192                  // 128 rows x 64 B
#define STAGE_B (4 * TILE_B)         // 32768 B (A0,A1,B0,B1)
#define NSTAGE 3
#define NCHUNK 16                    // 512 / 32

template <bool SPLIT>
__global__ void __launch_bounds__(256, 2) tc_gemm(
    const __half* __restrict__ A0, const __half* __restrict__ A1, long long aStr,
    const __half* __restrict__ B0, const __half* __restrict__ B1, long long bStr,
    const float* __restrict__ bias, int biasStr, int Nreal,
    float* __restrict__ outF, int outLd,
    __half* __restrict__ O0, __half* __restrict__ O1)
{
    extern __shared__ __align__(16) char dsm[];
    const uint32_t sbase = smem_u32(dsm);

    const int tid = threadIdx.x;
    const int warp = tid >> 5, lane = tid & 31;
    const int bz = blockIdx.z;
    const int m0 = blockIdx.y * 128, n0 = blockIdx.x * 128;
    const int warpM = (warp >> 2) * 64;   // 0 or 64
    const int warpN = (warp & 3) * 32;    // 0,32,64,96

    const char* gp[4];
    gp[0] = (const char*)A0 + ((size_t)bz * aStr + (size_t)m0 * D_) * 2;
    gp[1] = (const char*)A1 + ((size_t)bz * aStr + (size_t)m0 * D_) * 2;
    gp[2] = (const char*)B0 + ((size_t)bz * bStr + (size_t)n0 * D_) * 2;
    gp[3] = (const char*)B1 + ((size_t)bz * bStr + (size_t)n0 * D_) * 2;

    // cp.async write mapping (computed once): 2 chunks of 16B per thread per tile
    const int ldRow0 = tid >> 2, ldC0 = tid & 3;
    const int ldRow1 = (tid + 256) >> 2, ldC1 = (tid + 256) & 3;
    const uint32_t ldDst0 = (uint32_t)ldRow0 * 64 + (uint32_t)((ldC0 ^ ((ldRow0 >> 1) & 3)) << 4);
    const uint32_t ldDst1 = (uint32_t)ldRow1 * 64 + (uint32_t)((ldC1 ^ ((ldRow1 >> 1) & 3)) << 4);
    const size_t ldSrc0 = (size_t)ldRow0 * 1024 + ldC0 * 16;
    const size_t ldSrc1 = (size_t)ldRow1 * 1024 + ldC1 * 16;

    auto load_stage = [&](int kk, int buf) {
        const size_t koff = (size_t)kk * 64;   // 32 fp16 = 64B chunk
#pragma unroll
        for (int t = 0; t < 4; t++) {
            uint32_t sb = sbase + buf * STAGE_B + t * TILE_B;
            const char* g = gp[t] + koff;
            cp_async16(sb + ldDst0, g + ldSrc0);
            cp_async16(sb + ldDst1, g + ldSrc1);
        }
        cp_commit();
    };

    float acc[4][4][4];
#pragma unroll
    for (int i = 0; i < 4; i++)
#pragma unroll
        for (int j = 0; j < 4; j++)
#pragma unroll
            for (int r = 0; r < 4; r++) acc[i][j][r] = 0.0f;

    load_stage(0, 0);
    load_stage(1, 1);

    // per-lane ldmatrix addressing (swizzle value constant per lane)
    const int rowA = warpM + (lane & 15);
    const uint32_t swA = (uint32_t)((rowA >> 1) & 3);
    const uint32_t cA = (uint32_t)(lane >> 4);
    const uint32_t aBase = (uint32_t)rowA * 64;

    const int rowB = warpN + (lane & 7) + ((lane >> 4) & 1) * 8;
    const uint32_t swB = (uint32_t)((rowB >> 1) & 3);
    const uint32_t cB = (uint32_t)((lane >> 3) & 1);
    const uint32_t bBase = (uint32_t)rowB * 64;

    for (int kk = 0; kk < NCHUNK; kk++) {
        if (kk == NCHUNK - 1) cp_wait<0>(); else cp_wait<1>();
        __syncthreads();
        if (kk + 2 < NCHUNK) load_stage(kk + 2, (kk + 2) % NSTAGE);

        const uint32_t sb = sbase + (kk % NSTAGE) * STAGE_B;

#pragma unroll
        for (int ks = 0; ks < 2; ks++) {
            const uint32_t aOff = aBase + (((ks * 2 + cA) ^ swA) << 4);
            const uint32_t bOff = bBase + (((ks * 2 + cB) ^ swB) << 4);
            // ordered to minimize live fragment registers
            uint32_t a0f[4][4], b0f[2][4];
#pragma unroll
            for (int i = 0; i < 4; i++)
                ldsm4(a0f[i], sb + 0 * TILE_B + aOff + i * 1024);
#pragma unroll
            for (int jp = 0; jp < 2; jp++)
                ldsm4(b0f[jp], sb + 2 * TILE_B + bOff + jp * 1024);
#pragma unroll
            for (int i = 0; i < 4; i++)
#pragma unroll
                for (int j = 0; j < 4; j++)
                    mma16816(acc[i][j], a0f[i], b0f[j >> 1][(j & 1) * 2],
                             b0f[j >> 1][(j & 1) * 2 + 1]);
            {
                uint32_t b1f[2][4];
#pragma unroll
                for (int jp = 0; jp < 2; jp++)
                    ldsm4(b1f[jp], sb + 3 * TILE_B + bOff + jp * 1024);
#pragma unroll
                for (int i = 0; i < 4; i++)
#pragma unroll
                    for (int j = 0; j < 4; j++)
                        mma16816(acc[i][j], a0f[i], b1f[j >> 1][(j & 1) * 2],
                                 b1f[j >> 1][(j & 1) * 2 + 1]);
            }
            {
                uint32_t a1f[4][4];
#pragma unroll
                for (int i = 0; i < 4; i++)
                    ldsm4(a1f[i], sb + 1 * TILE_B + aOff + i * 1024);
#pragma unroll
                for (int i = 0; i < 4; i++)
#pragma unroll
                    for (int j = 0; j < 4; j++)
                        mma16816(acc[i][j], a1f[i], b0f[j >> 1][(j & 1) * 2],
                                 b0f[j >> 1][(j & 1) * 2 + 1]);
            }
        }
    }

    // ---------------- epilogue ----------------
    const int mBase = m0 + warpM + (lane >> 2);
    const int nBase = n0 + warpN + (lane & 3) * 2;
#pragma unroll
    for (int i = 0; i < 4; i++) {
#pragma unroll
        for (int j = 0; j < 4; j++) {
#pragma unroll
            for (int half = 0; half < 2; half++) {
                const int m = mBase + i * 16 + half * 8;
                const int n = nBase + j * 8;
                float v0 = acc[i][j][half * 2];
                float v1 = acc[i][j][half * 2 + 1];
                if (SPLIT) {
                    v0 = fmaxf(v0 + bias[bz * biasStr + n], 0.0f);
                    v1 = fmaxf(v1 + bias[bz * biasStr + n + 1], 0.0f);
                    __half a0, b0, a1, b1;
                    split2(v0, a0, b0);
                    split2(v1, a1, b1);
                    size_t ob = ((size_t)bz * B_ + m) * D_ + n;
                    *(__half2*)&O0[ob] = __half2(a0, a1);
                    *(__half2*)&O1[ob] = __half2(b0, b1);
                } else {
                    if (n < Nreal) {
                        v0 += bias[bz * biasStr + n];
                        v1 += bias[bz * biasStr + n + 1];
                    }
                    float2 vv = make_float2(v0, v1);
                    *(float2*)&outF[((size_t)m * K_ + bz) * outLd + n] = vv;
                }
            }
        }
    }
}

// ---------------------------------------------------------------------------
// Gating kernel (logits strided [b][k][CP_])
// ---------------------------------------------------------------------------
__global__ void __launch_bounds__(256) gating_kernel(
    const int* __restrict__ n_exp,
    float* __restrict__ out_logits,
    float* __restrict__ out_gates)
{
    extern __shared__ float sm[];
    float* sl = sm;             // [K_*C_]
    float* se = sm + K_ * C_;   // [K_*C_]
    __shared__ float sZ[K_], sG[K_ * K_], sgate[K_];

    const int b = blockIdx.x, tid = threadIdx.x;
    const int w = tid >> 5, lane = tid & 31;

    const float* lrow = g_logits + (size_t)b * K_ * CP_;
    for (int i = tid; i < K_ * C_; i += 256) {
        int k = i / C_, c = i - k * C_;
        sl[i] = lrow[(size_t)k * CP_ + c];
    }
    __syncthreads();

    {
        float m = -INFINITY;
        for (int c = lane; c < C_; c += 32) m = fmaxf(m, sl[w * C_ + c]);
#pragma unroll
        for (int o = 16; o > 0; o >>= 1) m = fmaxf(m, __shfl_xor_sync(0xffffffffu, m, o));
        float z = 0.0f;
        for (int c = lane; c < C_; c += 32) {
            float e = __expf(sl[w * C_ + c] - m);
            se[w * C_ + c] = e;
            z += e;
        }
#pragma unroll
        for (int o = 16; o > 0; o >>= 1) z += __shfl_xor_sync(0xffffffffu, z, o);
        if (lane == 0) sZ[w] = z;
    }
    __syncthreads();

    for (int p = w; p < 36; p += 8) {
        int i = 0, q = p;
        while (q >= K_ - i) { q -= (K_ - i); i++; }
        int j = i + q;
        float s = 0.0f;
        for (int c = lane; c < C_; c += 32) s += se[i * C_ + c] * se[j * C_ + c];
#pragma unroll
        for (int o = 16; o > 0; o >>= 1) s += __shfl_xor_sync(0xffffffffu, s, o);
        if (lane == 0) {
            float g = s / (sZ[i] * sZ[j]);
            sG[i * K_ + j] = g;
            sG[j * K_ + i] = g;
        }
    }
    __syncthreads();

    if (tid == 0) {
        float Smat[K_][K_], conf[K_], nrm[K_];
#pragma unroll
        for (int i = 0; i < K_; i++) {
            nrm[i] = sqrtf(sG[i * K_ + i]) + EPSV;
            conf[i] = 1.0f / sZ[i];
        }
#pragma unroll
        for (int i = 0; i < K_; i++)
#pragma unroll
            for (int j = 0; j < K_; j++)
                Smat[i][j] = sG[i * K_ + j] / (nrm[i] * nrm[j]);

        int bi = 0; float bv = conf[0];
#pragma unroll
        for (int i = 1; i < K_; i++) if (conf[i] > bv) { bv = conf[i]; bi = i; }
        bool sel[K_];
#pragma unroll
        for (int i = 0; i < K_; i++) sel[i] = false;
        sel[bi] = true;

        int n = n_exp[b];
        for (int t = 1; t < K_; t++) {
            float dist[K_];
#pragma unroll
            for (int i = 0; i < K_; i++) {
                if (sel[i]) dist[i] = -INFINITY;
                else {
                    float ms = -INFINITY;
#pragma unroll
                    for (int j = 0; j < K_; j++)
                        if (sel[j]) ms = fmaxf(ms, Smat[i][j]);
                    dist[i] = 1.0f - ms;
                }
            }
            int ai = 0; float av = dist[0];
#pragma unroll
            for (int i = 1; i < K_; i++) if (dist[i] > av) { av = dist[i]; ai = i; }
            if (t < n) sel[ai] = true;
        }

        float gl[K_], gm = -INFINITY;
#pragma unroll
        for (int i = 0; i < K_; i++) {
            gl[i] = (sel[i] ? conf[i] : NEGV) / TEMPV;
            gm = fmaxf(gm, gl[i]);
        }
        float gs = 0.0f;
#pragma unroll
        for (int i = 0; i < K_; i++) { gl[i] = __expf(gl[i] - gm); gs += gl[i]; }
#pragma unroll
        for (int i = 0; i < K_; i++) sgate[i] = gl[i] / gs;
    }
    __syncthreads();

    for (int c = tid; c < C_; c += 256) {
        float v = 0.0f;
#pragma unroll
        for (int k = 0; k < K_; k++) v += sgate[k] * sl[k * C_ + c];
        out_logits[(size_t)b * C_ + c] = v;
    }
    if (tid < K_) out_gates[(size_t)b * K_ + tid] = sgate[tid];
}

// ---------------------------------------------------------------------------
extern "C" void kernel_launch(void* const* d_in, const int* in_sizes, int n_in,
                              void* d_out, int out_size)
{
    const float* z    = (const float*)d_in[0];
    const int*   nexp = (const int*)d_in[1];
    const float* W1   = (const float*)d_in[2];
    const float* b1   = (const float*)d_in[3];
    const float* W2   = (const float*)d_in[4];
    const float* b2   = (const float*)d_in[5];
    float* out = (float*)d_out;

    __half *z0, *z1, *w10, *w11, *w20, *w21, *h0, *h1;
    float* lg;
    cudaGetSymbolAddress((void**)&z0, g_z0);   cudaGetSymbolAddress((void**)&z1, g_z1);
    cudaGetSymbolAddress((void**)&w10, g_w1t0); cudaGetSymbolAddress((void**)&w11, g_w1t1);
    cudaGetSymbolAddress((void**)&w20, g_w2t0); cudaGetSymbolAddress((void**)&w21, g_w2t1);
    cudaGetSymbolAddress((void**)&h0, g_h0);   cudaGetSymbolAddress((void**)&h1, g_h1);
    cudaGetSymbolAddress((void**)&lg, g_logits);

    cudaFuncSetAttribute(tc_gemm<true>,  cudaFuncAttributeMaxDynamicSharedMemorySize, NSTAGE * STAGE_B);
    cudaFuncSetAttribute(tc_gemm<false>, cudaFuncAttributeMaxDynamicSharedMemorySize, NSTAGE * STAGE_B);
    cudaFuncSetAttribute(gating_kernel,  cudaFuncAttributeMaxDynamicSharedMemorySize, 65536);

    // input conversions
    split2_kernel<<<(B_ * D_ + 255) / 256, 256>>>(z, z0, z1, B_ * D_);
    trsplit_kernel<<<dim3(D_ / 32, D_ / 32, K_), dim3(32, 8)>>>(W1, w10, w11, D_, D_);
    trsplit_kernel<<<dim3(CP_ / 32, D_ / 32, K_), dim3(32, 8)>>>(W2, w20, w21, C_, CP_);

    // GEMM1: h = relu(z @ W1 + b1), re-split into 2 fp16 limbs
    tc_gemm<true><<<dim3(D_ / 128, B_ / 128, K_), 256, NSTAGE * STAGE_B>>>(
        z0, z1, 0LL,
        w10, w11, (long long)D_ * D_,
        b1, D_, D_, nullptr, 0, h0, h1);

    // GEMM2: logits = h @ W2 + b2 (fp32, padded to CP_)
    tc_gemm<false><<<dim3(CP_ / 128, B_ / 128, K_), 256, NSTAGE * STAGE_B>>>(
        h0, h1, (long long)B_ * D_,
        w20, w21, (long long)CP_ * D_,
        b2, C_, C_, lg, CP_, nullptr, nullptr);

    // gating + combine
    gating_kernel<<<B_, 256, 2 * K_ * C_ * sizeof(float)>>>(
        nexp, out, out + (size_t)B_ * C_);
}

// round 8
// speedup vs baseline: 2.8552x; 1.1578x over previous
#include <cuda_runtime.h>
#include <cuda_fp16.h>
#include <cstdint>
#include <math.h>

#define B_ 8192
#define D_ 512
#define C_ 1000
#define CP_ 1024
#define CPS 1032     // padded smem stride (floats)
#define K_ 8
#define EPSV 1e-8f
#define TEMPV 0.2f
#define NEGV -10000.0f

// ---------------------------------------------------------------------------
// Scratch (__device__ globals)
// ---------------------------------------------------------------------------
__device__ __half g_z0[(size_t)B_ * D_];
__device__ __half g_z1[(size_t)B_ * D_];
__device__ __half g_w1t0[(size_t)K_ * D_ * D_];
__device__ __half g_w1t1[(size_t)K_ * D_ * D_];
__device__ __half g_w2t0[(size_t)K_ * CP_ * D_];
__device__ __half g_w2t1[(size_t)K_ * CP_ * D_];
__device__ __half g_h0[(size_t)K_ * B_ * D_];
__device__ __half g_h1[(size_t)K_ * B_ * D_];
__device__ float g_logits[(size_t)B_ * K_ * CP_];

// ---------------------------------------------------------------------------
// PTX helpers
// ---------------------------------------------------------------------------
__device__ __forceinline__ uint32_t smem_u32(const void* p) {
    uint32_t a;
    asm("{ .reg .u64 t; cvta.to.shared.u64 t, %1; cvt.u32.u64 %0, t; }" : "=r"(a) : "l"(p));
    return a;
}
__device__ __forceinline__ void cp_async16(uint32_t s, const void* g) {
    asm volatile("cp.async.cg.shared.global [%0], [%1], 16;" :: "r"(s), "l"(g));
}
__device__ __forceinline__ void cp_commit() { asm volatile("cp.async.commit_group;"); }
template <int N>
__device__ __forceinline__ void cp_wait() { asm volatile("cp.async.wait_group %0;" :: "n"(N)); }

__device__ __forceinline__ void ldsm4(uint32_t* r, uint32_t addr) {
    asm volatile("ldmatrix.sync.aligned.m8n8.x4.shared.b16 {%0,%1,%2,%3}, [%4];"
                 : "=r"(r[0]), "=r"(r[1]), "=r"(r[2]), "=r"(r[3]) : "r"(addr));
}
__device__ __forceinline__ void mma16816(float* c, const uint32_t* a, uint32_t b0, uint32_t b1) {
    asm volatile(
        "mma.sync.aligned.m16n8k16.row.col.f32.f16.f16.f32 "
        "{%0,%1,%2,%3}, {%4,%5,%6,%7}, {%8,%9}, {%0,%1,%2,%3};"
        : "+f"(c[0]), "+f"(c[1]), "+f"(c[2]), "+f"(c[3])
        : "r"(a[0]), "r"(a[1]), "r"(a[2]), "r"(a[3]), "r"(b0), "r"(b1));
}

// 2-limb fp16 split: x = a + b + O(2^-22 |x|)
__device__ __forceinline__ void split2(float x, __half& a, __half& b) {
    a = __float2half_rn(x);
    b = __float2half_rn(x - __half2float(a));
}

// ---------------------------------------------------------------------------
// Conversion kernels
// ---------------------------------------------------------------------------
__global__ void split2_kernel(const float* __restrict__ x, __half* __restrict__ o0,
                              __half* __restrict__ o1, int n4) {
    int i = blockIdx.x * blockDim.x + threadIdx.x;
    if (i < n4) {
        float4 v = ((const float4*)x)[i];
        __half a0, b0, a1, b1, a2, b2, a3, b3;
        split2(v.x, a0, b0); split2(v.y, a1, b1);
        split2(v.z, a2, b2); split2(v.w, a3, b3);
        ((__half2*)o0)[i * 2]     = __half2(a0, a1);
        ((__half2*)o0)[i * 2 + 1] = __half2(a2, a3);
        ((__half2*)o1)[i * 2]     = __half2(b0, b1);
        ((__half2*)o1)[i * 2 + 1] = __half2(b2, b3);
    }
}

// in: [K][D_][Nin] fp32 -> out: [K][Npad][D_] fp16 x2 (transposed, rows >= Nin zeroed)
__global__ void trsplit_kernel(const float* __restrict__ in, __half* __restrict__ o0,
                               __half* __restrict__ o1, int Nin, int Npad) {
    __shared__ float t[32][33];
    const int k = blockIdx.z;
    const int n0 = blockIdx.x * 32, d0 = blockIdx.y * 32;
    const int tx = threadIdx.x, ty = threadIdx.y;
    const float* src = in + (size_t)k * D_ * Nin;
#pragma unroll
    for (int r = 0; r < 4; r++) {
        int d = d0 + ty + r * 8, n = n0 + tx;
        t[ty + r * 8][tx] = (n < Nin) ? src[(size_t)d * Nin + n] : 0.0f;
    }
    __syncthreads();
    size_t obase = (size_t)k * Npad * D_;
#pragma unroll
    for (int r = 0; r < 4; r++) {
        int nl = ty + r * 8;
        float v = t[tx][nl];
        __half a, b;
        split2(v, a, b);
        size_t oi = obase + (size_t)(n0 + nl) * D_ + d0 + tx;
        o0[oi] = a; o1[oi] = b;
    }
}

// ---------------------------------------------------------------------------
// HMMA fp16 GEMM with 3-product 2-limb split.
// Block 128x128, BK=32, 256 threads (8 warps: 2x4), warp tile 64x32.
// 3-stage cp.async pipeline, XOR-swizzled packed smem, 2 CTAs/SM.
// ---------------------------------------------------------------------------
#define TILE_B 8192                  // 128 rows x 64 B
#define STAGE_B (4 * TILE_B)         // 32768 B (A0,A1,B0,B1)
#define NSTAGE 3
#define NCHUNK 16                    // 512 / 32

template <bool SPLIT>
__global__ void __launch_bounds__(256, 2) tc_gemm(
    const __half* __restrict__ A0, const __half* __restrict__ A1, long long aStr,
    const __half* __restrict__ B0, const __half* __restrict__ B1, long long bStr,
    const float* __restrict__ bias, int biasStr, int Nreal,
    float* __restrict__ outF, int outLd,
    __half* __restrict__ O0, __half* __restrict__ O1)
{
    extern __shared__ __align__(16) char dsm[];
    const uint32_t sbase = smem_u32(dsm);

    const int tid = threadIdx.x;
    const int warp = tid >> 5, lane = tid & 31;
    const int bz = blockIdx.z;
    const int m0 = blockIdx.y * 128, n0 = blockIdx.x * 128;
    const int warpM = (warp >> 2) * 64;   // 0 or 64
    const int warpN = (warp & 3) * 32;    // 0,32,64,96

    const char* gp[4];
    gp[0] = (const char*)A0 + ((size_t)bz * aStr + (size_t)m0 * D_) * 2;
    gp[1] = (const char*)A1 + ((size_t)bz * aStr + (size_t)m0 * D_) * 2;
    gp[2] = (const char*)B0 + ((size_t)bz * bStr + (size_t)n0 * D_) * 2;
    gp[3] = (const char*)B1 + ((size_t)bz * bStr + (size_t)n0 * D_) * 2;

    // cp.async write mapping: 2 chunks of 16B per thread per tile
    const int ldRow0 = tid >> 2, ldC0 = tid & 3;
    const int ldRow1 = (tid + 256) >> 2, ldC1 = (tid + 256) & 3;
    const uint32_t ldDst0 = (uint32_t)ldRow0 * 64 + (uint32_t)((ldC0 ^ ((ldRow0 >> 1) & 3)) << 4);
    const uint32_t ldDst1 = (uint32_t)ldRow1 * 64 + (uint32_t)((ldC1 ^ ((ldRow1 >> 1) & 3)) << 4);
    const size_t ldSrc0 = (size_t)ldRow0 * 1024 + ldC0 * 16;
    const size_t ldSrc1 = (size_t)ldRow1 * 1024 + ldC1 * 16;

    auto load_stage = [&](int kk, int buf) {
        const size_t koff = (size_t)kk * 64;
#pragma unroll
        for (int t = 0; t < 4; t++) {
            uint32_t sb = sbase + buf * STAGE_B + t * TILE_B;
            const char* g = gp[t] + koff;
            cp_async16(sb + ldDst0, g + ldSrc0);
            cp_async16(sb + ldDst1, g + ldSrc1);
        }
        cp_commit();
    };

    float acc[4][4][4];
#pragma unroll
    for (int i = 0; i < 4; i++)
#pragma unroll
        for (int j = 0; j < 4; j++)
#pragma unroll
            for (int r = 0; r < 4; r++) acc[i][j][r] = 0.0f;

    load_stage(0, 0);
    load_stage(1, 1);

    const int rowA = warpM + (lane & 15);
    const uint32_t swA = (uint32_t)((rowA >> 1) & 3);
    const uint32_t cA = (uint32_t)(lane >> 4);
    const uint32_t aBase = (uint32_t)rowA * 64;

    const int rowB = warpN + (lane & 7) + ((lane >> 4) & 1) * 8;
    const uint32_t swB = (uint32_t)((rowB >> 1) & 3);
    const uint32_t cB = (uint32_t)((lane >> 3) & 1);
    const uint32_t bBase = (uint32_t)rowB * 64;

    for (int kk = 0; kk < NCHUNK; kk++) {
        if (kk == NCHUNK - 1) cp_wait<0>(); else cp_wait<1>();
        __syncthreads();
        if (kk + 2 < NCHUNK) load_stage(kk + 2, (kk + 2) % NSTAGE);

        const uint32_t sb = sbase + (kk % NSTAGE) * STAGE_B;

#pragma unroll
        for (int ks = 0; ks < 2; ks++) {
            const uint32_t aOff = aBase + (((ks * 2 + cA) ^ swA) << 4);
            const uint32_t bOff = bBase + (((ks * 2 + cB) ^ swB) << 4);
            uint32_t a0f[4][4], b0f[2][4];
#pragma unroll
            for (int i = 0; i < 4; i++)
                ldsm4(a0f[i], sb + 0 * TILE_B + aOff + i * 1024);
#pragma unroll
            for (int jp = 0; jp < 2; jp++)
                ldsm4(b0f[jp], sb + 2 * TILE_B + bOff + jp * 1024);
#pragma unroll
            for (int i = 0; i < 4; i++)
#pragma unroll
                for (int j = 0; j < 4; j++)
                    mma16816(acc[i][j], a0f[i], b0f[j >> 1][(j & 1) * 2],
                             b0f[j >> 1][(j & 1) * 2 + 1]);
            {
                uint32_t b1f[2][4];
#pragma unroll
                for (int jp = 0; jp < 2; jp++)
                    ldsm4(b1f[jp], sb + 3 * TILE_B + bOff + jp * 1024);
#pragma unroll
                for (int i = 0; i < 4; i++)
#pragma unroll
                    for (int j = 0; j < 4; j++)
                        mma16816(acc[i][j], a0f[i], b1f[j >> 1][(j & 1) * 2],
                                 b1f[j >> 1][(j & 1) * 2 + 1]);
            }
            {
                uint32_t a1f[4][4];
#pragma unroll
                for (int i = 0; i < 4; i++)
                    ldsm4(a1f[i], sb + 1 * TILE_B + aOff + i * 1024);
#pragma unroll
                for (int i = 0; i < 4; i++)
#pragma unroll
                    for (int j = 0; j < 4; j++)
                        mma16816(acc[i][j], a1f[i], b0f[j >> 1][(j & 1) * 2],
                                 b0f[j >> 1][(j & 1) * 2 + 1]);
            }
        }
    }

    // ---------------- epilogue ----------------
    const int mBase = m0 + warpM + (lane >> 2);
    const int nBase = n0 + warpN + (lane & 3) * 2;

    // preload 8 bias values (n depends only on j/t)
    float bj[4][2];
#pragma unroll
    for (int j = 0; j < 4; j++)
#pragma unroll
        for (int t = 0; t < 2; t++) {
            int n = nBase + j * 8 + t;
            bj[j][t] = (SPLIT || n < Nreal) ? bias[bz * biasStr + n] : 0.0f;
        }

#pragma unroll
    for (int i = 0; i < 4; i++) {
#pragma unroll
        for (int j = 0; j < 4; j++) {
#pragma unroll
            for (int half = 0; half < 2; half++) {
                const int m = mBase + i * 16 + half * 8;
                const int n = nBase + j * 8;
                float v0 = acc[i][j][half * 2];
                float v1 = acc[i][j][half * 2 + 1];
                if (SPLIT) {
                    v0 = fmaxf(v0 + bj[j][0], 0.0f);
                    v1 = fmaxf(v1 + bj[j][1], 0.0f);
                    __half a0, b0, a1, b1;
                    split2(v0, a0, b0);
                    split2(v1, a1, b1);
                    size_t ob = ((size_t)bz * B_ + m) * D_ + n;
                    *(__half2*)&O0[ob] = __half2(a0, a1);
                    *(__half2*)&O1[ob] = __half2(b0, b1);
                } else {
                    v0 += bj[j][0];
                    v1 += bj[j][1];
                    float2 vv = make_float2(v0, v1);
                    *(float2*)&outF[((size_t)m * K_ + bz) * outLd + n] = vv;
                }
            }
        }
    }
}

// ---------------------------------------------------------------------------
// Gating kernel — vectorized float4; logits strided [b][k][CP_]
// smem: sl[K_*CPS] + se[K_*CPS]  (~66 KB)
// ---------------------------------------------------------------------------
__global__ void __launch_bounds__(256) gating_kernel(
    const int* __restrict__ n_exp,
    float* __restrict__ out_logits,
    float* __restrict__ out_gates)
{
    extern __shared__ float sm[];
    float* sl = sm;               // [K_][CPS]
    float* se = sm + K_ * CPS;    // [K_][CPS]
    __shared__ float sZ[K_], sG[K_ * K_], sgate[K_];

    const int b = blockIdx.x, tid = threadIdx.x;
    const int w = tid >> 5, lane = tid & 31;

    const float* lrow = g_logits + (size_t)b * K_ * CP_;
#pragma unroll
    for (int it = 0; it < 8; it++) {
        int idx = tid + it * 256;          // 0..2047
        int k = idx >> 8;                  // CP_/4 = 256 float4 per expert
        int c4 = (idx & 255) * 4;
        float4 v = *(const float4*)(lrow + (size_t)k * CP_ + c4);
        *(float4*)(sl + k * CPS + c4) = v;
    }
    __syncthreads();

    // per-expert softmax stats (warp w handles expert w); zero se in pad region
    {
        float m = -INFINITY;
#pragma unroll
        for (int it = 0; it < 8; it++) {
            int c = it * 128 + lane * 4;
            float4 v = *(const float4*)(sl + w * CPS + c);
            if (c + 0 < C_) m = fmaxf(m, v.x);
            if (c + 1 < C_) m = fmaxf(m, v.y);
            if (c + 2 < C_) m = fmaxf(m, v.z);
            if (c + 3 < C_) m = fmaxf(m, v.w);
        }
#pragma unroll
        for (int o = 16; o > 0; o >>= 1) m = fmaxf(m, __shfl_xor_sync(0xffffffffu, m, o));
        float z = 0.0f;
#pragma unroll
        for (int it = 0; it < 8; it++) {
            int c = it * 128 + lane * 4;
            float4 v = *(const float4*)(sl + w * CPS + c);
            float4 e;
            e.x = (c + 0 < C_) ? __expf(v.x - m) : 0.0f;
            e.y = (c + 1 < C_) ? __expf(v.y - m) : 0.0f;
            e.z = (c + 2 < C_) ? __expf(v.z - m) : 0.0f;
            e.w = (c + 3 < C_) ? __expf(v.w - m) : 0.0f;
            *(float4*)(se + w * CPS + c) = e;
            z += e.x + e.y + e.z + e.w;
        }
#pragma unroll
        for (int o = 16; o > 0; o >>= 1) z += __shfl_xor_sync(0xffffffffu, z, o);
        if (lane == 0) sZ[w] = z;
    }
    __syncthreads();

    // Gram of exp arrays (pad region is zero -> unmasked loops)
    for (int p = w; p < 36; p += 8) {
        int i = 0, q = p;
        while (q >= K_ - i) { q -= (K_ - i); i++; }
        int j = i + q;
        float s = 0.0f;
#pragma unroll
        for (int it = 0; it < 8; it++) {
            int c = it * 128 + lane * 4;
            float4 a = *(const float4*)(se + i * CPS + c);
            float4 bb = *(const float4*)(se + j * CPS + c);
            s += a.x * bb.x + a.y * bb.y + a.z * bb.z + a.w * bb.w;
        }
#pragma unroll
        for (int o = 16; o > 0; o >>= 1) s += __shfl_xor_sync(0xffffffffu, s, o);
        if (lane == 0) {
            float g = s / (sZ[i] * sZ[j]);
            sG[i * K_ + j] = g;
            sG[j * K_ + i] = g;
        }
    }
    __syncthreads();

    if (tid == 0) {
        float Smat[K_][K_], conf[K_], nrm[K_];
#pragma unroll
        for (int i = 0; i < K_; i++) {
            nrm[i] = sqrtf(sG[i * K_ + i]) + EPSV;
            conf[i] = 1.0f / sZ[i];
        }
#pragma unroll
        for (int i = 0; i < K_; i++)
#pragma unroll
            for (int j = 0; j < K_; j++)
                Smat[i][j] = sG[i * K_ + j] / (nrm[i] * nrm[j]);

        int bi = 0; float bv = conf[0];
#pragma unroll
        for (int i = 1; i < K_; i++) if (conf[i] > bv) { bv = conf[i]; bi = i; }
        bool sel[K_];
#pragma unroll
        for (int i = 0; i < K_; i++) sel[i] = false;
        sel[bi] = true;

        int n = n_exp[b];
        for (int t = 1; t < K_; t++) {
            float dist[K_];
#pragma unroll
            for (int i = 0; i < K_; i++) {
                if (sel[i]) dist[i] = -INFINITY;
                else {
                    float ms = -INFINITY;
#pragma unroll
                    for (int j = 0; j < K_; j++)
                        if (sel[j]) ms = fmaxf(ms, Smat[i][j]);
                    dist[i] = 1.0f - ms;
                }
            }
            int ai = 0; float av = dist[0];
#pragma unroll
            for (int i = 1; i < K_; i++) if (dist[i] > av) { av = dist[i]; ai = i; }
            if (t < n) sel[ai] = true;
        }

        float gl[K_], gm = -INFINITY;
#pragma unroll
        for (int i = 0; i < K_; i++) {
            gl[i] = (sel[i] ? conf[i] : NEGV) / TEMPV;
            gm = fmaxf(gm, gl[i]);
        }
        float gs = 0.0f;
#pragma unroll
        for (int i = 0; i < K_; i++) { gl[i] = __expf(gl[i] - gm); gs += gl[i]; }
#pragma unroll
        for (int i = 0; i < K_; i++) sgate[i] = gl[i] / gs;
    }
    __syncthreads();

    // gated combine (float4; C_ = 250 * 4)
    if (tid < 250) {
        int c = tid * 4;
        float4 acc4 = make_float4(0.f, 0.f, 0.f, 0.f);
#pragma unroll
        for (int k = 0; k < K_; k++) {
            float g = sgate[k];
            float4 v = *(const float4*)(sl + k * CPS + c);
            acc4.x += g * v.x; acc4.y += g * v.y;
            acc4.z += g * v.z; acc4.w += g * v.w;
        }
        *(float4*)(out_logits + (size_t)b * C_ + c) = acc4;
    }
    if (tid < K_) out_gates[(size_t)b * K_ + tid] = sgate[tid];
}

// ---------------------------------------------------------------------------
extern "C" void kernel_launch(void* const* d_in, const int* in_sizes, int n_in,
                              void* d_out, int out_size)
{
    const float* z    = (const float*)d_in[0];
    const int*   nexp = (const int*)d_in[1];
    const float* W1   = (const float*)d_in[2];
    const float* b1   = (const float*)d_in[3];
    const float* W2   = (const float*)d_in[4];
    const float* b2   = (const float*)d_in[5];
    float* out = (float*)d_out;

    __half *z0, *z1, *w10, *w11, *w20, *w21, *h0, *h1;
    float* lg;
    cudaGetSymbolAddress((void**)&z0, g_z0);   cudaGetSymbolAddress((void**)&z1, g_z1);
    cudaGetSymbolAddress((void**)&w10, g_w1t0); cudaGetSymbolAddress((void**)&w11, g_w1t1);
    cudaGetSymbolAddress((void**)&w20, g_w2t0); cudaGetSymbolAddress((void**)&w21, g_w2t1);
    cudaGetSymbolAddress((void**)&h0, g_h0);   cudaGetSymbolAddress((void**)&h1, g_h1);
    cudaGetSymbolAddress((void**)&lg, g_logits);

    const int gate_smem = 2 * K_ * CPS * sizeof(float);
    cudaFuncSetAttribute(tc_gemm<true>,  cudaFuncAttributeMaxDynamicSharedMemorySize, NSTAGE * STAGE_B);
    cudaFuncSetAttribute(tc_gemm<false>, cudaFuncAttributeMaxDynamicSharedMemorySize, NSTAGE * STAGE_B);
    cudaFuncSetAttribute(gating_kernel,  cudaFuncAttributeMaxDynamicSharedMemorySize, gate_smem);

    // input conversions
    split2_kernel<<<(B_ * D_ / 4 + 255) / 256, 256>>>(z, z0, z1, B_ * D_ / 4);
    trsplit_kernel<<<dim3(D_ / 32, D_ / 32, K_), dim3(32, 8)>>>(W1, w10, w11, D_, D_);
    trsplit_kernel<<<dim3(CP_ / 32, D_ / 32, K_), dim3(32, 8)>>>(W2, w20, w21, C_, CP_);

    // GEMM1: h = relu(z @ W1 + b1), re-split into 2 fp16 limbs
    tc_gemm<true><<<dim3(D_ / 128, B_ / 128, K_), 256, NSTAGE * STAGE_B>>>(
        z0, z1, 0LL,
        w10, w11, (long long)D_ * D_,
        b1, D_, D_, nullptr, 0, h0, h1);

    // GEMM2: logits = h @ W2 + b2 (fp32, padded to CP_)
    tc_gemm<false><<<dim3(CP_ / 128, B_ / 128, K_), 256, NSTAGE * STAGE_B>>>(
        h0, h1, (long long)B_ * D_,
        w20, w21, (long long)CP_ * D_,
        b2, C_, C_, lg, CP_, nullptr, nullptr);

    // gating + combine
    gating_kernel<<<B_, 256, gate_smem>>>(nexp, out, out + (size_t)B_ * C_);
}